// round 3
// baseline (speedup 1.0000x reference)
#include <cuda_runtime.h>
#include <cuda_bf16.h>
#include <cstdint>

// Problem constants
#define BB   4
#define NN   2048
#define DD   1024
#define HH   16
#define HDD  64
#define MTOT (BB * NN)   // 8192

// ---------------- scratch (device globals: no allocations allowed) ----------
__device__ float g_q[MTOT * DD];
__device__ float g_k[MTOT * DD];
__device__ float g_v[MTOT * DD];
__device__ float g_a[MTOT * DD];

// ---------------- SGEMM: C[M,N] = A[M,K] @ W[K,N] + bias -------------------
// 128x128 tile, BK=8, 256 threads, 8x8 per thread, fp32.
#define TM 128
#define TN 128
#define TK 8

__global__ __launch_bounds__(256)
void sgemm_bias(const float* __restrict__ A, const float* __restrict__ W,
                const float* __restrict__ bias, float* __restrict__ C,
                int M, int Nn, int K) {
    __shared__ float As[TK][TM + 4];   // transposed A tile, padded
    __shared__ float Bs[TK][TN];

    const int tid = threadIdx.x;          // 0..255
    const int tx = tid & 15;              // 0..15  -> cols tx*8..tx*8+7
    const int ty = tid >> 4;              // 0..15  -> rows ty*8..ty*8+7
    const int m0 = blockIdx.y * TM;
    const int n0 = blockIdx.x * TN;

    float acc[8][8];
    #pragma unroll
    for (int i = 0; i < 8; i++)
        #pragma unroll
        for (int j = 0; j < 8; j++) acc[i][j] = 0.f;

    // load assignments
    const int a_r = tid >> 1;             // 0..127
    const int a_q = (tid & 1) * 4;        // 0 or 4
    const int b_k = tid >> 5;             // 0..7
    const int b_c = (tid & 31) * 4;       // 0..124

    const float* Ag = A + (size_t)(m0 + a_r) * K + a_q;
    const float* Wg = W + (size_t)b_k * Nn + n0 + b_c;

    for (int k0 = 0; k0 < K; k0 += TK) {
        float4 av = *(const float4*)(Ag + k0);
        As[a_q + 0][a_r] = av.x;
        As[a_q + 1][a_r] = av.y;
        As[a_q + 2][a_r] = av.z;
        As[a_q + 3][a_r] = av.w;
        *(float4*)&Bs[b_k][b_c] = *(const float4*)(Wg + (size_t)k0 * Nn);
        __syncthreads();

        #pragma unroll
        for (int kk = 0; kk < TK; kk++) {
            float4 a0 = *(const float4*)&As[kk][ty * 8];
            float4 a1 = *(const float4*)&As[kk][ty * 8 + 4];
            float4 b0 = *(const float4*)&Bs[kk][tx * 8];
            float4 b1 = *(const float4*)&Bs[kk][tx * 8 + 4];
            float ar[8] = {a0.x, a0.y, a0.z, a0.w, a1.x, a1.y, a1.z, a1.w};
            float br[8] = {b0.x, b0.y, b0.z, b0.w, b1.x, b1.y, b1.z, b1.w};
            #pragma unroll
            for (int i = 0; i < 8; i++)
                #pragma unroll
                for (int j = 0; j < 8; j++)
                    acc[i][j] += ar[i] * br[j];
        }
        __syncthreads();
    }

    // epilogue with bias
    float bv[8];
    #pragma unroll
    for (int j = 0; j < 8; j++) bv[j] = bias[n0 + tx * 8 + j];

    #pragma unroll
    for (int i = 0; i < 8; i++) {
        float* Crow = C + (size_t)(m0 + ty * 8 + i) * Nn + n0 + tx * 8;
        float4 r0 = make_float4(acc[i][0] + bv[0], acc[i][1] + bv[1],
                                acc[i][2] + bv[2], acc[i][3] + bv[3]);
        float4 r1 = make_float4(acc[i][4] + bv[4], acc[i][5] + bv[5],
                                acc[i][6] + bv[6], acc[i][7] + bv[7]);
        *(float4*)(Crow)     = r0;
        *(float4*)(Crow + 4) = r1;
    }
}

// ---------------- causal flash attention, fp32 ------------------------------
// grid: x = N/64 query tiles (32), y = B*H (64). block: 256 threads (16x16).
// Each block: 64 queries x HD=64, iterates key blocks kb <= qtile (causal skip).
#define QS_STRIDE 68   // padded stride for transposed Q/K tiles

__global__ __launch_bounds__(256)
void flash_attn(const float* __restrict__ Q, const float* __restrict__ K,
                const float* __restrict__ V, float* __restrict__ O) {
    extern __shared__ float sm[];
    float* Qs = sm;                              // [64][68]  Qs[d*68 + r]
    float* Ks = sm + 64 * QS_STRIDE;             // [64][68]  Ks[d*68 + c]
    float* Vs = sm + 2 * 64 * QS_STRIDE;         // [64][64]  Vs[k*64 + d]
    float* Ps = Vs + 64 * 64;                    // [64][64]  Ps[r*64 + c]

    const int tid = threadIdx.x;
    const int tx = tid & 15;      // key-col / hd-col group
    const int ty = tid >> 4;      // query-row group
    const int bh = blockIdx.y;
    const int b = bh >> 4, h = bh & 15;
    const int q0 = blockIdx.x * 64;
    const size_t base = (size_t)b * NN * DD + h * HDD;

    // load Q tile (scaled by 1/sqrt(64)), transposed
    {
        const int d = tid & 63, r0 = tid >> 6;
        #pragma unroll
        for (int r = r0; r < 64; r += 4)
            Qs[d * QS_STRIDE + r] = Q[base + (size_t)(q0 + r) * DD + d] * 0.125f;
    }

    float m_i[4], l_i[4], o[4][4];
    #pragma unroll
    for (int i = 0; i < 4; i++) {
        m_i[i] = -1e30f; l_i[i] = 0.f;
        #pragma unroll
        for (int j = 0; j < 4; j++) o[i][j] = 0.f;
    }

    const int nkb = blockIdx.x + 1;   // causal: only key blocks <= query block
    for (int kb = 0; kb < nkb; kb++) {
        const int k0 = kb * 64;
        __syncthreads();   // protect previous-iter smem reads before overwrite
        {
            const int d = tid & 63, r0 = tid >> 6;
            #pragma unroll
            for (int c = r0; c < 64; c += 4)
                Ks[d * QS_STRIDE + c] = K[base + (size_t)(k0 + c) * DD + d];
            #pragma unroll
            for (int k = r0; k < 64; k += 4)
                Vs[k * 64 + d] = V[base + (size_t)(k0 + k) * DD + d];
        }
        __syncthreads();

        // S = Q @ K^T  (64x64, 4x4 per thread)
        float s[4][4];
        #pragma unroll
        for (int i = 0; i < 4; i++)
            #pragma unroll
            for (int j = 0; j < 4; j++) s[i][j] = 0.f;

        #pragma unroll 8
        for (int dd = 0; dd < 64; dd++) {
            float4 a = *(const float4*)&Qs[dd * QS_STRIDE + ty * 4];
            float4 c = *(const float4*)&Ks[dd * QS_STRIDE + tx * 4];
            float ar[4] = {a.x, a.y, a.z, a.w};
            float cr[4] = {c.x, c.y, c.z, c.w};
            #pragma unroll
            for (int i = 0; i < 4; i++)
                #pragma unroll
                for (int j = 0; j < 4; j++)
                    s[i][j] += ar[i] * cr[j];
        }

        if (k0 == q0) {   // diagonal block: causal mask (strictly upper)
            #pragma unroll
            for (int i = 0; i < 4; i++)
                #pragma unroll
                for (int j = 0; j < 4; j++)
                    if (tx * 4 + j > ty * 4 + i) s[i][j] = -1e30f;
        }

        // online softmax update per row
        #pragma unroll
        for (int i = 0; i < 4; i++) {
            float rm = fmaxf(fmaxf(s[i][0], s[i][1]), fmaxf(s[i][2], s[i][3]));
            #pragma unroll
            for (int off = 8; off >= 1; off >>= 1)
                rm = fmaxf(rm, __shfl_xor_sync(0xffffffffu, rm, off));
            const float mn = fmaxf(m_i[i], rm);
            const float alpha = __expf(m_i[i] - mn);
            m_i[i] = mn;
            float rs = 0.f;
            #pragma unroll
            for (int j = 0; j < 4; j++) {
                s[i][j] = __expf(s[i][j] - mn);
                rs += s[i][j];
            }
            #pragma unroll
            for (int off = 8; off >= 1; off >>= 1)
                rs += __shfl_xor_sync(0xffffffffu, rs, off);
            l_i[i] = l_i[i] * alpha + rs;
            #pragma unroll
            for (int j = 0; j < 4; j++) o[i][j] *= alpha;
            *(float4*)&Ps[(ty * 4 + i) * 64 + tx * 4] =
                make_float4(s[i][0], s[i][1], s[i][2], s[i][3]);
        }
        __syncthreads();

        // O += P @ V  (thread cols = hd dims tx*4..tx*4+3)
        #pragma unroll 8
        for (int k = 0; k < 64; k++) {
            float4 vv = *(const float4*)&Vs[k * 64 + tx * 4];
            float vr[4] = {vv.x, vv.y, vv.z, vv.w};
            float pk[4];
            #pragma unroll
            for (int i = 0; i < 4; i++) pk[i] = Ps[(ty * 4 + i) * 64 + k];
            #pragma unroll
            for (int i = 0; i < 4; i++)
                #pragma unroll
                for (int j = 0; j < 4; j++)
                    o[i][j] += pk[i] * vr[j];
        }
    }

    // epilogue: normalize, write to [B,N,H*HD] (concat-heads layout)
    #pragma unroll
    for (int i = 0; i < 4; i++) {
        const float inv = 1.f / l_i[i];
        float4 r = make_float4(o[i][0] * inv, o[i][1] * inv,
                               o[i][2] * inv, o[i][3] * inv);
        *(float4*)&O[base + (size_t)(q0 + ty * 4 + i) * DD + tx * 4] = r;
    }
}

// ---------------- launch ----------------------------------------------------
extern "C" void kernel_launch(void* const* d_in, const int* in_sizes, int n_in,
                              void* d_out, int out_size) {
    const float* x  = (const float*)d_in[0];
    const float* Wq = (const float*)d_in[1];
    const float* bq = (const float*)d_in[2];
    const float* Wk = (const float*)d_in[3];
    const float* bk = (const float*)d_in[4];
    const float* Wv = (const float*)d_in[5];
    const float* bv = (const float*)d_in[6];
    const float* Wo = (const float*)d_in[7];
    const float* bo = (const float*)d_in[8];
    float* out = (float*)d_out;

    float *q, *k, *v, *a;
    cudaGetSymbolAddress((void**)&q, g_q);
    cudaGetSymbolAddress((void**)&k, g_k);
    cudaGetSymbolAddress((void**)&v, g_v);
    cudaGetSymbolAddress((void**)&a, g_a);

    const int smem_flash = (2 * 64 * QS_STRIDE + 2 * 64 * 64) * sizeof(float);
    cudaFuncSetAttribute(flash_attn, cudaFuncAttributeMaxDynamicSharedMemorySize,
                         smem_flash);

    dim3 gg(DD / TN, MTOT / TM);   // (8, 64)
    sgemm_bias<<<gg, 256>>>(x, Wq, bq, q, MTOT, DD, DD);
    sgemm_bias<<<gg, 256>>>(x, Wk, bk, k, MTOT, DD, DD);
    sgemm_bias<<<gg, 256>>>(x, Wv, bv, v, MTOT, DD, DD);

    flash_attn<<<dim3(NN / 64, BB * HH), 256, smem_flash>>>(q, k, v, a);

    sgemm_bias<<<gg, 256>>>(a, Wo, bo, out, MTOT, DD, DD);
}

// round 5
// speedup vs baseline: 1.7296x; 1.7296x over previous
#include <cuda_runtime.h>
#include <cuda_bf16.h>
#include <cstdint>

// Problem constants
#define BB   4
#define NN   2048
#define DD   1024
#define HH   16
#define HDD  64
#define MTOT (BB * NN)   // 8192

// ---------------- scratch (device globals: no allocations allowed) ----------
__device__ float g_q[MTOT * DD];
__device__ float g_k[MTOT * DD];
__device__ float g_v[MTOT * DD];
__device__ float g_a[MTOT * DD];

// bf16 hi/lo splits (x and attention-output reuse the same buffers)
__device__ __align__(256) __nv_bfloat16 g_xhi[MTOT * DD];
__device__ __align__(256) __nv_bfloat16 g_xlo[MTOT * DD];
// transposed weight splits: [n][k] K-major, bf16
__device__ __align__(256) __nv_bfloat16 g_wqh[DD * DD];
__device__ __align__(256) __nv_bfloat16 g_wql[DD * DD];
__device__ __align__(256) __nv_bfloat16 g_wkh[DD * DD];
__device__ __align__(256) __nv_bfloat16 g_wkl[DD * DD];
__device__ __align__(256) __nv_bfloat16 g_wvh[DD * DD];
__device__ __align__(256) __nv_bfloat16 g_wvl[DD * DD];
__device__ __align__(256) __nv_bfloat16 g_woh[DD * DD];
__device__ __align__(256) __nv_bfloat16 g_wol[DD * DD];

// =====================  small PTX helpers (arch-portable)  ==================
__device__ __forceinline__ uint32_t smem_u32(const void* p) {
    uint32_t a;
    asm("{ .reg .u64 t; cvta.to.shared.u64 t, %1; cvt.u32.u64 %0, t; }"
        : "=r"(a) : "l"(p));
    return a;
}
__device__ __forceinline__ void cpa16(uint32_t dst, const void* src) {
    asm volatile("cp.async.cg.shared.global [%0], [%1], 16;\n"
                 :: "r"(dst), "l"(src));
}
__device__ __forceinline__ void cp_commit() {
    asm volatile("cp.async.commit_group;\n" ::: "memory");
}
__device__ __forceinline__ void cp_wait1() {
    asm volatile("cp.async.wait_group 1;\n" ::: "memory");
}
__device__ __forceinline__ void cp_wait0() {
    asm volatile("cp.async.wait_group 0;\n" ::: "memory");
}
__device__ __forceinline__ void ldsm4(uint32_t* r, uint32_t addr) {
    asm volatile("ldmatrix.sync.aligned.m8n8.x4.shared.b16 {%0,%1,%2,%3}, [%4];\n"
                 : "=r"(r[0]), "=r"(r[1]), "=r"(r[2]), "=r"(r[3]) : "r"(addr));
}
__device__ __forceinline__ void mma16816(float* d, const uint32_t* a,
                                         uint32_t b0, uint32_t b1) {
    asm volatile(
        "mma.sync.aligned.m16n8k16.row.col.f32.bf16.bf16.f32 "
        "{%0,%1,%2,%3}, {%4,%5,%6,%7}, {%8,%9}, {%0,%1,%2,%3};\n"
        : "+f"(d[0]), "+f"(d[1]), "+f"(d[2]), "+f"(d[3])
        : "r"(a[0]), "r"(a[1]), "r"(a[2]), "r"(a[3]), "r"(b0), "r"(b1));
}
__device__ __forceinline__ uint32_t sw128(uint32_t off) {
    return off ^ ((off >> 3) & 0x70);
}

// =====================  fp32 -> bf16 hi/lo split kernels  ===================
__global__ __launch_bounds__(256)
void split_fp32(const float4* __restrict__ in, uint2* __restrict__ hi,
                uint2* __restrict__ lo) {
    const int i = blockIdx.x * 256 + threadIdx.x;   // 4 elems per thread
    float4 v = in[i];
    __nv_bfloat16 h[4], l[4];
    float vv[4] = {v.x, v.y, v.z, v.w};
    #pragma unroll
    for (int j = 0; j < 4; j++) {
        h[j] = __float2bfloat16(vv[j]);
        l[j] = __float2bfloat16(vv[j] - __bfloat162float(h[j]));
    }
    hi[i] = *(const uint2*)h;
    lo[i] = *(const uint2*)l;
}

// W[k][n] -> Wt_hi/lo[n][k] (K-major rows for the B operand)
__global__ __launch_bounds__(256)
void wsplit_t(const float* __restrict__ W, __nv_bfloat16* __restrict__ th,
              __nv_bfloat16* __restrict__ tl) {
    __shared__ float t[32][33];
    const int n0 = blockIdx.x * 32, k0 = blockIdx.y * 32;
    const int tx = threadIdx.x, ty = threadIdx.y;   // (32,8)
    #pragma unroll
    for (int i = 0; i < 32; i += 8)
        t[ty + i][tx] = W[(size_t)(k0 + ty + i) * DD + n0 + tx];
    __syncthreads();
    #pragma unroll
    for (int i = 0; i < 32; i += 8) {
        const float v = t[tx][ty + i];  // = W[k0+tx][n0+ty+i]
        const __nv_bfloat16 h = __float2bfloat16(v);
        const __nv_bfloat16 l = __float2bfloat16(v - __bfloat162float(h));
        const size_t o = (size_t)(n0 + ty + i) * DD + k0 + tx;
        th[o] = h; tl[o] = l;
    }
}

// ============  mma.sync split-bf16 GEMM: C = A@W + bias  ====================
// CTA tile 128x128, K-chunks of 64 bf16 (128B swizzled rows), 3-stage
// cp.async ring. 8 warps in 2(M)x4(N); 64x32 per warp via m16n8k16 HMMA.
// A: [M][K] bf16 hi/lo row-major. B: [N][K] bf16 hi/lo (K-major rows).
#define STAGE_BYTES 65536
#define OFF_AHI 0
#define OFF_ALO 16384
#define OFF_BHI 32768
#define OFF_BLO 49152
#define NCHUNK  16

__global__ __launch_bounds__(256)
void gemm_mma(const __nv_bfloat16* __restrict__ Ahi,
              const __nv_bfloat16* __restrict__ Alo,
              const __nv_bfloat16* __restrict__ Bhi,
              const __nv_bfloat16* __restrict__ Blo,
              const float* __restrict__ bias, float* __restrict__ C) {
    extern __shared__ __align__(1024) char smem[];

    const int tid = threadIdx.x;
    const int wid = tid >> 5, lane = tid & 31;
    const int m0 = blockIdx.y * 128;
    const int n0 = blockIdx.x * 128;
    const uint32_t sbase = smem_u32(smem);

    const __nv_bfloat16* pAhi = Ahi + (size_t)m0 * DD;
    const __nv_bfloat16* pAlo = Alo + (size_t)m0 * DD;
    const __nv_bfloat16* pBhi = Bhi + (size_t)n0 * DD;
    const __nv_bfloat16* pBlo = Blo + (size_t)n0 * DD;

    // stage loader: 4 tiles of 128 rows x 128B, swizzled cp.async
    auto load_stage = [&](int stage, int ch) {
        const uint32_t sb = sbase + stage * STAGE_BYTES;
        const int coff = ch * 64;
        #pragma unroll
        for (int it = 0; it < 4; it++) {
            const int i = tid + it * 256;        // 0..1023
            const int row = i >> 3, seg = i & 7;
            const uint32_t sw = sw128((uint32_t)(row * 128 + seg * 16));
            const size_t g = (size_t)row * DD + coff + seg * 8;
            cpa16(sb + OFF_AHI + sw, pAhi + g);
            cpa16(sb + OFF_ALO + sw, pAlo + g);
            cpa16(sb + OFF_BHI + sw, pBhi + g);
            cpa16(sb + OFF_BLO + sw, pBlo + g);
        }
        cp_commit();
    };

    // warp tiling: wm in {0,1} (64 rows), wn in {0..3} (32 cols)
    const int wm = wid & 1, wn = wid >> 1;

    // ldmatrix per-lane rows (canonical x4 mappings)
    int a_row[4], b_row[2];
    #pragma unroll
    for (int i = 0; i < 4; i++)
        a_row[i] = wm * 64 + i * 16 + (lane & 7) + ((lane >> 3) & 1) * 8;
    #pragma unroll
    for (int j = 0; j < 2; j++)
        b_row[j] = wn * 32 + j * 16 + (lane & 7) + ((lane >> 4) & 1) * 8;
    const int cbA = lane >> 4;         // A: chunk +0/+1 by lane group
    const int cbB = (lane >> 3) & 1;   // B: chunk +0/+1 by lane group

    float acc[4][4][4];
    #pragma unroll
    for (int i = 0; i < 4; i++)
        #pragma unroll
        for (int j = 0; j < 4; j++)
            #pragma unroll
            for (int q = 0; q < 4; q++) acc[i][j][q] = 0.f;

    load_stage(0, 0);
    load_stage(1, 1);

    for (int c = 0; c < NCHUNK; c++) {
        if (c == NCHUNK - 1) cp_wait0(); else cp_wait1();
        __syncthreads();
        if (c + 2 < NCHUNK) load_stage((c + 2) % 3, c + 2);

        const uint32_t sb = sbase + (c % 3) * STAGE_BYTES;
        #pragma unroll
        for (int s = 0; s < 4; s++) {   // four k16 steps per 64-elem chunk
            uint32_t ah[4][4], al[4][4], bh[2][4], bl[2][4];
            #pragma unroll
            for (int i = 0; i < 4; i++) {
                const uint32_t off = (uint32_t)(a_row[i] * 128) +
                    (uint32_t)(((2 * s + cbA) ^ (a_row[i] & 7)) << 4);
                ldsm4(ah[i], sb + OFF_AHI + off);
                ldsm4(al[i], sb + OFF_ALO + off);
            }
            #pragma unroll
            for (int j = 0; j < 2; j++) {
                const uint32_t off = (uint32_t)(b_row[j] * 128) +
                    (uint32_t)(((2 * s + cbB) ^ (b_row[j] & 7)) << 4);
                ldsm4(bh[j], sb + OFF_BHI + off);
                ldsm4(bl[j], sb + OFF_BLO + off);
            }
            // term 1: hi*hi  (16 independent MMAs)
            #pragma unroll
            for (int i = 0; i < 4; i++)
                #pragma unroll
                for (int jj = 0; jj < 4; jj++)
                    mma16816(acc[i][jj], ah[i],
                             bh[jj >> 1][(jj & 1) * 2], bh[jj >> 1][(jj & 1) * 2 + 1]);
            // term 2: hi*lo
            #pragma unroll
            for (int i = 0; i < 4; i++)
                #pragma unroll
                for (int jj = 0; jj < 4; jj++)
                    mma16816(acc[i][jj], ah[i],
                             bl[jj >> 1][(jj & 1) * 2], bl[jj >> 1][(jj & 1) * 2 + 1]);
            // term 3: lo*hi
            #pragma unroll
            for (int i = 0; i < 4; i++)
                #pragma unroll
                for (int jj = 0; jj < 4; jj++)
                    mma16816(acc[i][jj], al[i],
                             bh[jj >> 1][(jj & 1) * 2], bh[jj >> 1][(jj & 1) * 2 + 1]);
        }
    }

    // epilogue: fragment layout -> C, with bias (float2 stores)
    const int mbase = m0 + wm * 64 + (lane >> 2);
    const int nbase = n0 + wn * 32 + (lane & 3) * 2;
    #pragma unroll
    for (int jj = 0; jj < 4; jj++) {
        const int col = nbase + jj * 8;
        const float b0 = __ldg(&bias[col]);
        const float b1 = __ldg(&bias[col + 1]);
        #pragma unroll
        for (int i = 0; i < 4; i++) {
            const int r0 = mbase + i * 16;
            float2 v0 = make_float2(acc[i][jj][0] + b0, acc[i][jj][1] + b1);
            float2 v1 = make_float2(acc[i][jj][2] + b0, acc[i][jj][3] + b1);
            *(float2*)(C + (size_t)r0 * DD + col) = v0;
            *(float2*)(C + (size_t)(r0 + 8) * DD + col) = v1;
        }
    }
}

// ---------------- causal flash attention, fp32 (unchanged) ------------------
#define QS_STRIDE 68

__global__ __launch_bounds__(256)
void flash_attn(const float* __restrict__ Q, const float* __restrict__ K,
                const float* __restrict__ V, float* __restrict__ O) {
    extern __shared__ float sm[];
    float* Qs = sm;
    float* Ks = sm + 64 * QS_STRIDE;
    float* Vs = sm + 2 * 64 * QS_STRIDE;
    float* Ps = Vs + 64 * 64;

    const int tid = threadIdx.x;
    const int tx = tid & 15;
    const int ty = tid >> 4;
    const int bh = blockIdx.y;
    const int b = bh >> 4, h = bh & 15;
    const int q0 = blockIdx.x * 64;
    const size_t base = (size_t)b * NN * DD + h * HDD;

    {
        const int d = tid & 63, r0 = tid >> 6;
        #pragma unroll
        for (int r = r0; r < 64; r += 4)
            Qs[d * QS_STRIDE + r] = Q[base + (size_t)(q0 + r) * DD + d] * 0.125f;
    }

    float m_i[4], l_i[4], o[4][4];
    #pragma unroll
    for (int i = 0; i < 4; i++) {
        m_i[i] = -1e30f; l_i[i] = 0.f;
        #pragma unroll
        for (int j = 0; j < 4; j++) o[i][j] = 0.f;
    }

    const int nkb = blockIdx.x + 1;
    for (int kb = 0; kb < nkb; kb++) {
        const int k0 = kb * 64;
        __syncthreads();
        {
            const int d = tid & 63, r0 = tid >> 6;
            #pragma unroll
            for (int c = r0; c < 64; c += 4)
                Ks[d * QS_STRIDE + c] = K[base + (size_t)(k0 + c) * DD + d];
            #pragma unroll
            for (int k = r0; k < 64; k += 4)
                Vs[k * 64 + d] = V[base + (size_t)(k0 + k) * DD + d];
        }
        __syncthreads();

        float s[4][4];
        #pragma unroll
        for (int i = 0; i < 4; i++)
            #pragma unroll
            for (int j = 0; j < 4; j++) s[i][j] = 0.f;

        #pragma unroll 8
        for (int dd = 0; dd < 64; dd++) {
            float4 a = *(const float4*)&Qs[dd * QS_STRIDE + ty * 4];
            float4 c = *(const float4*)&Ks[dd * QS_STRIDE + tx * 4];
            float ar[4] = {a.x, a.y, a.z, a.w};
            float cr[4] = {c.x, c.y, c.z, c.w};
            #pragma unroll
            for (int i = 0; i < 4; i++)
                #pragma unroll
                for (int j = 0; j < 4; j++)
                    s[i][j] += ar[i] * cr[j];
        }

        if (k0 == q0) {
            #pragma unroll
            for (int i = 0; i < 4; i++)
                #pragma unroll
                for (int j = 0; j < 4; j++)
                    if (tx * 4 + j > ty * 4 + i) s[i][j] = -1e30f;
        }

        #pragma unroll
        for (int i = 0; i < 4; i++) {
            float rm = fmaxf(fmaxf(s[i][0], s[i][1]), fmaxf(s[i][2], s[i][3]));
            #pragma unroll
            for (int off = 8; off >= 1; off >>= 1)
                rm = fmaxf(rm, __shfl_xor_sync(0xffffffffu, rm, off));
            const float mn = fmaxf(m_i[i], rm);
            const float alpha = __expf(m_i[i] - mn);
            m_i[i] = mn;
            float rs = 0.f;
            #pragma unroll
            for (int j = 0; j < 4; j++) {
                s[i][j] = __expf(s[i][j] - mn);
                rs += s[i][j];
            }
            #pragma unroll
            for (int off = 8; off >= 1; off >>= 1)
                rs += __shfl_xor_sync(0xffffffffu, rs, off);
            l_i[i] = l_i[i] * alpha + rs;
            #pragma unroll
            for (int j = 0; j < 4; j++) o[i][j] *= alpha;
            *(float4*)&Ps[(ty * 4 + i) * 64 + tx * 4] =
                make_float4(s[i][0], s[i][1], s[i][2], s[i][3]);
        }
        __syncthreads();

        #pragma unroll 8
        for (int k = 0; k < 64; k++) {
            float4 vv = *(const float4*)&Vs[k * 64 + tx * 4];
            float vr[4] = {vv.x, vv.y, vv.z, vv.w};
            float pk[4];
            #pragma unroll
            for (int i = 0; i < 4; i++) pk[i] = Ps[(ty * 4 + i) * 64 + k];
            #pragma unroll
            for (int i = 0; i < 4; i++)
                #pragma unroll
                for (int j = 0; j < 4; j++)
                    o[i][j] += pk[i] * vr[j];
        }
    }

    #pragma unroll
    for (int i = 0; i < 4; i++) {
        const float inv = 1.f / l_i[i];
        float4 r = make_float4(o[i][0] * inv, o[i][1] * inv,
                               o[i][2] * inv, o[i][3] * inv);
        *(float4*)&O[base + (size_t)(q0 + ty * 4 + i) * DD + tx * 4] = r;
    }
}

// ---------------- launch ----------------------------------------------------
extern "C" void kernel_launch(void* const* d_in, const int* in_sizes, int n_in,
                              void* d_out, int out_size) {
    const float* x  = (const float*)d_in[0];
    const float* Wq = (const float*)d_in[1];
    const float* bq = (const float*)d_in[2];
    const float* Wk = (const float*)d_in[3];
    const float* bk = (const float*)d_in[4];
    const float* Wv = (const float*)d_in[5];
    const float* bv = (const float*)d_in[6];
    const float* Wo = (const float*)d_in[7];
    const float* bo = (const float*)d_in[8];
    float* out = (float*)d_out;

    float *q, *k, *v, *a;
    cudaGetSymbolAddress((void**)&q, g_q);
    cudaGetSymbolAddress((void**)&k, g_k);
    cudaGetSymbolAddress((void**)&v, g_v);
    cudaGetSymbolAddress((void**)&a, g_a);
    __nv_bfloat16 *xh, *xl, *wqh, *wql, *wkh, *wkl, *wvh, *wvl, *woh, *wol;
    cudaGetSymbolAddress((void**)&xh, g_xhi);
    cudaGetSymbolAddress((void**)&xl, g_xlo);
    cudaGetSymbolAddress((void**)&wqh, g_wqh);
    cudaGetSymbolAddress((void**)&wql, g_wql);
    cudaGetSymbolAddress((void**)&wkh, g_wkh);
    cudaGetSymbolAddress((void**)&wkl, g_wkl);
    cudaGetSymbolAddress((void**)&wvh, g_wvh);
    cudaGetSymbolAddress((void**)&wvl, g_wvl);
    cudaGetSymbolAddress((void**)&woh, g_woh);
    cudaGetSymbolAddress((void**)&wol, g_wol);

    const int smem_gemm = 3 * STAGE_BYTES;   // 196608
    cudaFuncSetAttribute(gemm_mma, cudaFuncAttributeMaxDynamicSharedMemorySize,
                         smem_gemm);
    const int smem_flash = (2 * 64 * QS_STRIDE + 2 * 64 * 64) * sizeof(float);
    cudaFuncSetAttribute(flash_attn, cudaFuncAttributeMaxDynamicSharedMemorySize,
                         smem_flash);

    // weight split+transpose (K-major B operands)
    dim3 wsg(32, 32), wsb(32, 8);
    wsplit_t<<<wsg, wsb>>>(Wq, wqh, wql);
    wsplit_t<<<wsg, wsb>>>(Wk, wkh, wkl);
    wsplit_t<<<wsg, wsb>>>(Wv, wvh, wvl);
    wsplit_t<<<wsg, wsb>>>(Wo, woh, wol);

    // x split
    split_fp32<<<(MTOT * DD) / 1024, 256>>>((const float4*)x, (uint2*)xh, (uint2*)xl);

    dim3 gg(DD / 128, MTOT / 128);   // (8, 64)
    gemm_mma<<<gg, 256, smem_gemm>>>(xh, xl, wqh, wql, bq, q);
    gemm_mma<<<gg, 256, smem_gemm>>>(xh, xl, wkh, wkl, bk, k);
    gemm_mma<<<gg, 256, smem_gemm>>>(xh, xl, wvh, wvl, bv, v);

    flash_attn<<<dim3(NN / 64, BB * HH), 256, smem_flash>>>(q, k, v, a);

    // attention-output split (reuses x split buffers) + output projection
    split_fp32<<<(MTOT * DD) / 1024, 256>>>((const float4*)a, (uint2*)xh, (uint2*)xl);
    gemm_mma<<<gg, 256, smem_gemm>>>(xh, xl, woh, wol, bo, out);
}

// round 7
// speedup vs baseline: 3.0602x; 1.7693x over previous
#include <cuda_runtime.h>
#include <cuda_bf16.h>
#include <cstdint>

// Problem constants
#define BB   4
#define NN   2048
#define DD   1024
#define HH   16
#define HDD  64
#define MTOT (BB * NN)   // 8192

// ---------------- scratch (device globals: no allocations allowed) ----------
// x split (reused after flash as attention-output split)
__device__ __align__(256) __nv_bfloat16 g_xhi[MTOT * DD];
__device__ __align__(256) __nv_bfloat16 g_xlo[MTOT * DD];
// QKV projections, bf16 hi/lo (Q pre-scaled by 1/8)
__device__ __align__(256) __nv_bfloat16 g_qh[MTOT * DD];
__device__ __align__(256) __nv_bfloat16 g_ql[MTOT * DD];
__device__ __align__(256) __nv_bfloat16 g_kh[MTOT * DD];
__device__ __align__(256) __nv_bfloat16 g_kl[MTOT * DD];
__device__ __align__(256) __nv_bfloat16 g_vh[MTOT * DD];
__device__ __align__(256) __nv_bfloat16 g_vl[MTOT * DD];
// transposed weight splits: [n][k] K-major, bf16
__device__ __align__(256) __nv_bfloat16 g_wqh[DD * DD];
__device__ __align__(256) __nv_bfloat16 g_wql[DD * DD];
__device__ __align__(256) __nv_bfloat16 g_wkh[DD * DD];
__device__ __align__(256) __nv_bfloat16 g_wkl[DD * DD];
__device__ __align__(256) __nv_bfloat16 g_wvh[DD * DD];
__device__ __align__(256) __nv_bfloat16 g_wvl[DD * DD];
__device__ __align__(256) __nv_bfloat16 g_woh[DD * DD];
__device__ __align__(256) __nv_bfloat16 g_wol[DD * DD];

// =====================  small PTX helpers (arch-portable)  ==================
__device__ __forceinline__ uint32_t smem_u32(const void* p) {
    uint32_t a;
    asm("{ .reg .u64 t; cvta.to.shared.u64 t, %1; cvt.u32.u64 %0, t; }"
        : "=r"(a) : "l"(p));
    return a;
}
__device__ __forceinline__ void cpa16(uint32_t dst, const void* src) {
    asm volatile("cp.async.cg.shared.global [%0], [%1], 16;\n"
                 :: "r"(dst), "l"(src));
}
__device__ __forceinline__ void cp_commit() {
    asm volatile("cp.async.commit_group;\n" ::: "memory");
}
__device__ __forceinline__ void cp_wait1() {
    asm volatile("cp.async.wait_group 1;\n" ::: "memory");
}
__device__ __forceinline__ void cp_wait0() {
    asm volatile("cp.async.wait_group 0;\n" ::: "memory");
}
__device__ __forceinline__ void ldsm4(uint32_t* r, uint32_t addr) {
    asm volatile("ldmatrix.sync.aligned.m8n8.x4.shared.b16 {%0,%1,%2,%3}, [%4];\n"
                 : "=r"(r[0]), "=r"(r[1]), "=r"(r[2]), "=r"(r[3]) : "r"(addr));
}
__device__ __forceinline__ void ldsm4t(uint32_t* r, uint32_t addr) {
    asm volatile("ldmatrix.sync.aligned.m8n8.x4.trans.shared.b16 {%0,%1,%2,%3}, [%4];\n"
                 : "=r"(r[0]), "=r"(r[1]), "=r"(r[2]), "=r"(r[3]) : "r"(addr));
}
__device__ __forceinline__ void mma16816(float* d, const uint32_t* a,
                                         uint32_t b0, uint32_t b1) {
    asm volatile(
        "mma.sync.aligned.m16n8k16.row.col.f32.bf16.bf16.f32 "
        "{%0,%1,%2,%3}, {%4,%5,%6,%7}, {%8,%9}, {%0,%1,%2,%3};\n"
        : "+f"(d[0]), "+f"(d[1]), "+f"(d[2]), "+f"(d[3])
        : "r"(a[0]), "r"(a[1]), "r"(a[2]), "r"(a[3]), "r"(b0), "r"(b1));
}
__device__ __forceinline__ uint32_t sw128(uint32_t off) {
    return off ^ ((off >> 3) & 0x70);
}
// split (x,y) into packed bf16x2 hi and lo residual pairs
__device__ __forceinline__ void splitpack(float x, float y, uint32_t& h, uint32_t& l) {
    __nv_bfloat16 hx = __float2bfloat16(x);
    __nv_bfloat16 hy = __float2bfloat16(y);
    __nv_bfloat16 lx = __float2bfloat16(x - __bfloat162float(hx));
    __nv_bfloat16 ly = __float2bfloat16(y - __bfloat162float(hy));
    __nv_bfloat162 hv; hv.x = hx; hv.y = hy;
    __nv_bfloat162 lv; lv.x = lx; lv.y = ly;
    h = *reinterpret_cast<uint32_t*>(&hv);
    l = *reinterpret_cast<uint32_t*>(&lv);
}

// =====================  fp32 -> bf16 hi/lo split kernels  ===================
__global__ __launch_bounds__(256)
void split_fp32(const float4* __restrict__ in, uint2* __restrict__ hi,
                uint2* __restrict__ lo) {
    const int i = blockIdx.x * 256 + threadIdx.x;
    float4 v = in[i];
    __nv_bfloat16 h[4], l[4];
    float vv[4] = {v.x, v.y, v.z, v.w};
    #pragma unroll
    for (int j = 0; j < 4; j++) {
        h[j] = __float2bfloat16(vv[j]);
        l[j] = __float2bfloat16(vv[j] - __bfloat162float(h[j]));
    }
    hi[i] = *(const uint2*)h;
    lo[i] = *(const uint2*)l;
}

// W[k][n] -> Wt_hi/lo[n][k] (K-major rows for the B operand)
__global__ __launch_bounds__(256)
void wsplit_t(const float* __restrict__ W, __nv_bfloat16* __restrict__ th,
              __nv_bfloat16* __restrict__ tl) {
    __shared__ float t[32][33];
    const int n0 = blockIdx.x * 32, k0 = blockIdx.y * 32;
    const int tx = threadIdx.x, ty = threadIdx.y;   // (32,8)
    #pragma unroll
    for (int i = 0; i < 32; i += 8)
        t[ty + i][tx] = W[(size_t)(k0 + ty + i) * DD + n0 + tx];
    __syncthreads();
    #pragma unroll
    for (int i = 0; i < 32; i += 8) {
        const float v = t[tx][ty + i];
        const __nv_bfloat16 h = __float2bfloat16(v);
        const __nv_bfloat16 l = __float2bfloat16(v - __bfloat162float(h));
        const size_t o = (size_t)(n0 + ty + i) * DD + k0 + tx;
        th[o] = h; tl[o] = l;
    }
}

// ============  mma.sync split-bf16 GEMM: C = (A@W + bias)*scale  ============
// SPLIT=0: fp32 C.  SPLIT=1: bf16 hi/lo outputs Ch/Cl.
#define STAGE_BYTES 65536
#define OFF_AHI 0
#define OFF_ALO 16384
#define OFF_BHI 32768
#define OFF_BLO 49152
#define NCHUNK  16

template<int SPLIT>
__global__ __launch_bounds__(256)
void gemm_mma(const __nv_bfloat16* __restrict__ Ahi,
              const __nv_bfloat16* __restrict__ Alo,
              const __nv_bfloat16* __restrict__ Bhi,
              const __nv_bfloat16* __restrict__ Blo,
              const float* __restrict__ bias, float* __restrict__ C,
              __nv_bfloat16* __restrict__ Ch, __nv_bfloat16* __restrict__ Cl,
              float scale) {
    extern __shared__ __align__(1024) char smem[];

    const int tid = threadIdx.x;
    const int wid = tid >> 5, lane = tid & 31;
    const int m0 = blockIdx.y * 128;
    const int n0 = blockIdx.x * 128;
    const uint32_t sbase = smem_u32(smem);

    const __nv_bfloat16* pAhi = Ahi + (size_t)m0 * DD;
    const __nv_bfloat16* pAlo = Alo + (size_t)m0 * DD;
    const __nv_bfloat16* pBhi = Bhi + (size_t)n0 * DD;
    const __nv_bfloat16* pBlo = Blo + (size_t)n0 * DD;

    auto load_stage = [&](int stage, int ch) {
        const uint32_t sb = sbase + stage * STAGE_BYTES;
        const int coff = ch * 64;
        #pragma unroll
        for (int it = 0; it < 4; it++) {
            const int i = tid + it * 256;
            const int row = i >> 3, seg = i & 7;
            const uint32_t sw = sw128((uint32_t)(row * 128 + seg * 16));
            const size_t g = (size_t)row * DD + coff + seg * 8;
            cpa16(sb + OFF_AHI + sw, pAhi + g);
            cpa16(sb + OFF_ALO + sw, pAlo + g);
            cpa16(sb + OFF_BHI + sw, pBhi + g);
            cpa16(sb + OFF_BLO + sw, pBlo + g);
        }
        cp_commit();
    };

    const int wm = wid & 1, wn = wid >> 1;

    int a_row[4], b_row[2];
    #pragma unroll
    for (int i = 0; i < 4; i++)
        a_row[i] = wm * 64 + i * 16 + (lane & 7) + ((lane >> 3) & 1) * 8;
    #pragma unroll
    for (int j = 0; j < 2; j++)
        b_row[j] = wn * 32 + j * 16 + (lane & 7) + ((lane >> 4) & 1) * 8;
    const int cbA = lane >> 4;
    const int cbB = (lane >> 3) & 1;

    float acc[4][4][4];
    #pragma unroll
    for (int i = 0; i < 4; i++)
        #pragma unroll
        for (int j = 0; j < 4; j++)
            #pragma unroll
            for (int q = 0; q < 4; q++) acc[i][j][q] = 0.f;

    load_stage(0, 0);
    load_stage(1, 1);

    for (int c = 0; c < NCHUNK; c++) {
        if (c == NCHUNK - 1) cp_wait0(); else cp_wait1();
        __syncthreads();
        if (c + 2 < NCHUNK) load_stage((c + 2) % 3, c + 2);

        const uint32_t sb = sbase + (c % 3) * STAGE_BYTES;
        #pragma unroll
        for (int s = 0; s < 4; s++) {
            uint32_t ah[4][4], al[4][4], bh[2][4], bl[2][4];
            #pragma unroll
            for (int i = 0; i < 4; i++) {
                const uint32_t off = (uint32_t)(a_row[i] * 128) +
                    (uint32_t)(((2 * s + cbA) ^ (a_row[i] & 7)) << 4);
                ldsm4(ah[i], sb + OFF_AHI + off);
                ldsm4(al[i], sb + OFF_ALO + off);
            }
            #pragma unroll
            for (int j = 0; j < 2; j++) {
                const uint32_t off = (uint32_t)(b_row[j] * 128) +
                    (uint32_t)(((2 * s + cbB) ^ (b_row[j] & 7)) << 4);
                ldsm4(bh[j], sb + OFF_BHI + off);
                ldsm4(bl[j], sb + OFF_BLO + off);
            }
            #pragma unroll
            for (int i = 0; i < 4; i++)
                #pragma unroll
                for (int jj = 0; jj < 4; jj++)
                    mma16816(acc[i][jj], ah[i],
                             bh[jj >> 1][(jj & 1) * 2], bh[jj >> 1][(jj & 1) * 2 + 1]);
            #pragma unroll
            for (int i = 0; i < 4; i++)
                #pragma unroll
                for (int jj = 0; jj < 4; jj++)
                    mma16816(acc[i][jj], ah[i],
                             bl[jj >> 1][(jj & 1) * 2], bl[jj >> 1][(jj & 1) * 2 + 1]);
            #pragma unroll
            for (int i = 0; i < 4; i++)
                #pragma unroll
                for (int jj = 0; jj < 4; jj++)
                    mma16816(acc[i][jj], al[i],
                             bh[jj >> 1][(jj & 1) * 2], bh[jj >> 1][(jj & 1) * 2 + 1]);
        }
    }

    const int mbase = m0 + wm * 64 + (lane >> 2);
    const int nbase = n0 + wn * 32 + (lane & 3) * 2;
    #pragma unroll
    for (int jj = 0; jj < 4; jj++) {
        const int col = nbase + jj * 8;
        const float b0 = __ldg(&bias[col]);
        const float b1 = __ldg(&bias[col + 1]);
        #pragma unroll
        for (int i = 0; i < 4; i++) {
            const int r0 = mbase + i * 16;
            const float v0 = (acc[i][jj][0] + b0) * scale;
            const float v1 = (acc[i][jj][1] + b1) * scale;
            const float v2 = (acc[i][jj][2] + b0) * scale;
            const float v3 = (acc[i][jj][3] + b1) * scale;
            if (SPLIT) {
                uint32_t h0, l0, h1, l1;
                splitpack(v0, v1, h0, l0);
                splitpack(v2, v3, h1, l1);
                *(uint32_t*)(Ch + (size_t)r0 * DD + col) = h0;
                *(uint32_t*)(Cl + (size_t)r0 * DD + col) = l0;
                *(uint32_t*)(Ch + (size_t)(r0 + 8) * DD + col) = h1;
                *(uint32_t*)(Cl + (size_t)(r0 + 8) * DD + col) = l1;
            } else {
                *(float2*)(C + (size_t)r0 * DD + col) = make_float2(v0, v1);
                *(float2*)(C + (size_t)(r0 + 8) * DD + col) = make_float2(v2, v3);
            }
        }
    }
}

// ============  causal flash attention, split-bf16 mma.sync  =================
// Br=128 queries/CTA, Bc=64 keys/block, 8 warps (16 rows each).
// Q resident in smem; K/V double-buffered via cp.async.
// smem: Qh(16K)+Ql(16K) + 2 stages x [Kh,Kl,Vh,Vl](8K each)=64K -> 96K total.
#define FQH 0
#define FQL 16384
#define FST0 32768
#define FSTG 32768
#define FS_KH 0
#define FS_KL 8192
#define FS_VH 16384
#define FS_VL 24576
#define FA_SMEM 98304

__global__ __launch_bounds__(256, 2)
void flash_mma(const __nv_bfloat16* __restrict__ Qh, const __nv_bfloat16* __restrict__ Ql,
               const __nv_bfloat16* __restrict__ Kh, const __nv_bfloat16* __restrict__ Kl,
               const __nv_bfloat16* __restrict__ Vh, const __nv_bfloat16* __restrict__ Vl,
               __nv_bfloat16* __restrict__ Oh, __nv_bfloat16* __restrict__ Ol) {
    extern __shared__ __align__(1024) char smem[];
    const uint32_t sb = smem_u32(smem);
    const int tid = threadIdx.x, wid = tid >> 5, lane = tid & 31;
    const int qt = blockIdx.x, bh = blockIdx.y;
    const int b = bh >> 4, h = bh & 15;
    const int q0 = qt * 128;
    const size_t gbase = (size_t)b * NN * DD + h * HDD;

    // Q tile (hi+lo), 128 rows x 128B, swizzled
    {
        const __nv_bfloat16* qh = Qh + gbase + (size_t)q0 * DD;
        const __nv_bfloat16* ql = Ql + gbase + (size_t)q0 * DD;
        #pragma unroll
        for (int it = 0; it < 4; it++) {
            const int i = tid + it * 256;
            const int row = i >> 3, seg = i & 7;
            const uint32_t sw = sw128((uint32_t)(row * 128 + seg * 16));
            const size_t g = (size_t)row * DD + seg * 8;
            cpa16(sb + FQH + sw, qh + g);
            cpa16(sb + FQL + sw, ql + g);
        }
    }
    auto load_kv = [&](int stage, int kb) {
        const uint32_t s0 = sb + FST0 + stage * FSTG;
        const int k0 = kb * 64;
        #pragma unroll
        for (int it = 0; it < 2; it++) {
            const int i = tid + it * 256;     // 0..511
            const int row = i >> 3, seg = i & 7;
            const uint32_t sw = sw128((uint32_t)(row * 128 + seg * 16));
            const size_t g = gbase + (size_t)(k0 + row) * DD + seg * 8;
            cpa16(s0 + FS_KH + sw, Kh + g);
            cpa16(s0 + FS_KL + sw, Kl + g);
            cpa16(s0 + FS_VH + sw, Vh + g);
            cpa16(s0 + FS_VL + sw, Vl + g);
        }
        cp_commit();
    };
    load_kv(0, 0);   // Q cpa16s commit in this group too

    float m0 = -1e30f, m1 = -1e30f, l0 = 0.f, l1 = 0.f;
    float oacc[8][4];
    #pragma unroll
    for (int j = 0; j < 8; j++)
        #pragma unroll
        for (int q = 0; q < 4; q++) oacc[j][q] = 0.f;

    const int nkb = 2 * qt + 2;
    for (int kb = 0; kb < nkb; kb++) {
        cp_wait0();
        __syncthreads();
        if (kb + 1 < nkb) load_kv((kb + 1) & 1, kb + 1);

        const int k0 = kb * 64;
        const bool active = (k0 <= q0 + wid * 16 + 15);   // warp-uniform
        if (active) {
            const uint32_t st = sb + FST0 + (kb & 1) * FSTG;

            // ---- S = Q K^T (3-term split) ----
            float sacc[8][4];
            #pragma unroll
            for (int j = 0; j < 8; j++)
                #pragma unroll
                for (int q = 0; q < 4; q++) sacc[j][q] = 0.f;

            #pragma unroll
            for (int s = 0; s < 4; s++) {
                uint32_t ah[4], al[4];
                const int arow = wid * 16 + (lane & 15);
                const uint32_t aoff = sw128((uint32_t)(arow * 128 + (s * 2 + (lane >> 4)) * 16));
                ldsm4(ah, sb + FQH + aoff);
                ldsm4(al, sb + FQL + aoff);
                #pragma unroll
                for (int jg = 0; jg < 4; jg++) {
                    const int brow = jg * 16 + (lane & 7) + ((lane >> 4) & 1) * 8;
                    const uint32_t boff = sw128((uint32_t)(brow * 128 + (s * 2 + ((lane >> 3) & 1)) * 16));
                    uint32_t bh4[4], bl4[4];
                    ldsm4(bh4, st + FS_KH + boff);
                    ldsm4(bl4, st + FS_KL + boff);
                    mma16816(sacc[2 * jg],     ah, bh4[0], bh4[1]);
                    mma16816(sacc[2 * jg + 1], ah, bh4[2], bh4[3]);
                    mma16816(sacc[2 * jg],     ah, bl4[0], bl4[1]);
                    mma16816(sacc[2 * jg + 1], ah, bl4[2], bl4[3]);
                    mma16816(sacc[2 * jg],     al, bh4[0], bh4[1]);
                    mma16816(sacc[2 * jg + 1], al, bh4[2], bh4[3]);
                }
            }

            // ---- causal mask ----
            const int row0 = q0 + wid * 16 + (lane >> 2);
            if (k0 + 63 > q0 + wid * 16) {
                #pragma unroll
                for (int j = 0; j < 8; j++) {
                    const int c = k0 + j * 8 + (lane & 3) * 2;
                    if (c > row0)       sacc[j][0] = -1e30f;
                    if (c + 1 > row0)   sacc[j][1] = -1e30f;
                    if (c > row0 + 8)   sacc[j][2] = -1e30f;
                    if (c + 1 > row0 + 8) sacc[j][3] = -1e30f;
                }
            }

            // ---- online softmax ----
            float mx0 = -1e30f, mx1 = -1e30f;
            #pragma unroll
            for (int j = 0; j < 8; j++) {
                mx0 = fmaxf(mx0, fmaxf(sacc[j][0], sacc[j][1]));
                mx1 = fmaxf(mx1, fmaxf(sacc[j][2], sacc[j][3]));
            }
            mx0 = fmaxf(mx0, __shfl_xor_sync(0xffffffffu, mx0, 1));
            mx0 = fmaxf(mx0, __shfl_xor_sync(0xffffffffu, mx0, 2));
            mx1 = fmaxf(mx1, __shfl_xor_sync(0xffffffffu, mx1, 1));
            mx1 = fmaxf(mx1, __shfl_xor_sync(0xffffffffu, mx1, 2));
            const float m0n = fmaxf(m0, mx0), m1n = fmaxf(m1, mx1);
            const float a0 = __expf(m0 - m0n), a1 = __expf(m1 - m1n);
            m0 = m0n; m1 = m1n;
            float s0 = 0.f, s1 = 0.f;
            #pragma unroll
            for (int j = 0; j < 8; j++) {
                sacc[j][0] = __expf(sacc[j][0] - m0n);
                sacc[j][1] = __expf(sacc[j][1] - m0n);
                sacc[j][2] = __expf(sacc[j][2] - m1n);
                sacc[j][3] = __expf(sacc[j][3] - m1n);
                s0 += sacc[j][0] + sacc[j][1];
                s1 += sacc[j][2] + sacc[j][3];
            }
            s0 += __shfl_xor_sync(0xffffffffu, s0, 1);
            s0 += __shfl_xor_sync(0xffffffffu, s0, 2);
            s1 += __shfl_xor_sync(0xffffffffu, s1, 1);
            s1 += __shfl_xor_sync(0xffffffffu, s1, 2);
            l0 = l0 * a0 + s0;
            l1 = l1 * a1 + s1;
            #pragma unroll
            for (int j = 0; j < 8; j++) {
                oacc[j][0] *= a0; oacc[j][1] *= a0;
                oacc[j][2] *= a1; oacc[j][3] *= a1;
            }

            // ---- O += P @ V (3-term split) ----
            #pragma unroll
            for (int t = 0; t < 4; t++) {
                uint32_t pah[4], pal[4];
                splitpack(sacc[2 * t][0],     sacc[2 * t][1],     pah[0], pal[0]);
                splitpack(sacc[2 * t][2],     sacc[2 * t][3],     pah[1], pal[1]);
                splitpack(sacc[2 * t + 1][0], sacc[2 * t + 1][1], pah[2], pal[2]);
                splitpack(sacc[2 * t + 1][2], sacc[2 * t + 1][3], pah[3], pal[3]);
                const int jq = lane >> 3;
                const int vrow = t * 16 + (jq & 1) * 8 + (lane & 7);
                #pragma unroll
                for (int g = 0; g < 4; g++) {
                    const uint32_t voff = sw128((uint32_t)(vrow * 128 + (g * 16 + (jq >> 1) * 8) * 2));
                    uint32_t vh4[4], vl4[4];
                    ldsm4t(vh4, st + FS_VH + voff);
                    ldsm4t(vl4, st + FS_VL + voff);
                    mma16816(oacc[2 * g],     pah, vh4[0], vh4[1]);
                    mma16816(oacc[2 * g + 1], pah, vh4[2], vh4[3]);
                    mma16816(oacc[2 * g],     pah, vl4[0], vl4[1]);
                    mma16816(oacc[2 * g + 1], pah, vl4[2], vl4[3]);
                    mma16816(oacc[2 * g],     pal, vh4[0], vh4[1]);
                    mma16816(oacc[2 * g + 1], pal, vh4[2], vh4[3]);
                }
            }
        }
    }

    // ---- epilogue: normalize + split into bf16 hi/lo outputs ----
    const float i0 = 1.f / l0, i1 = 1.f / l1;
    const size_t r0o = gbase + (size_t)(q0 + wid * 16 + (lane >> 2)) * DD;
    const size_t r1o = r0o + (size_t)8 * DD;
    #pragma unroll
    for (int j = 0; j < 8; j++) {
        const int c = j * 8 + (lane & 3) * 2;
        uint32_t h0, lo0, h1, lo1;
        splitpack(oacc[j][0] * i0, oacc[j][1] * i0, h0, lo0);
        splitpack(oacc[j][2] * i1, oacc[j][3] * i1, h1, lo1);
        *(uint32_t*)(Oh + r0o + c) = h0;
        *(uint32_t*)(Ol + r0o + c) = lo0;
        *(uint32_t*)(Oh + r1o + c) = h1;
        *(uint32_t*)(Ol + r1o + c) = lo1;
    }
}

// ---------------- launch ----------------------------------------------------
extern "C" void kernel_launch(void* const* d_in, const int* in_sizes, int n_in,
                              void* d_out, int out_size) {
    const float* x  = (const float*)d_in[0];
    const float* Wq = (const float*)d_in[1];
    const float* bq = (const float*)d_in[2];
    const float* Wk = (const float*)d_in[3];
    const float* bk = (const float*)d_in[4];
    const float* Wv = (const float*)d_in[5];
    const float* bv = (const float*)d_in[6];
    const float* Wo = (const float*)d_in[7];
    const float* bo = (const float*)d_in[8];
    float* out = (float*)d_out;

    __nv_bfloat16 *xh, *xl, *qh, *ql, *kh, *kl, *vh, *vl;
    __nv_bfloat16 *wqh, *wql, *wkh, *wkl, *wvh, *wvl, *woh, *wol;
    cudaGetSymbolAddress((void**)&xh, g_xhi);
    cudaGetSymbolAddress((void**)&xl, g_xlo);
    cudaGetSymbolAddress((void**)&qh, g_qh);
    cudaGetSymbolAddress((void**)&ql, g_ql);
    cudaGetSymbolAddress((void**)&kh, g_kh);
    cudaGetSymbolAddress((void**)&kl, g_kl);
    cudaGetSymbolAddress((void**)&vh, g_vh);
    cudaGetSymbolAddress((void**)&vl, g_vl);
    cudaGetSymbolAddress((void**)&wqh, g_wqh);
    cudaGetSymbolAddress((void**)&wql, g_wql);
    cudaGetSymbolAddress((void**)&wkh, g_wkh);
    cudaGetSymbolAddress((void**)&wkl, g_wkl);
    cudaGetSymbolAddress((void**)&wvh, g_wvh);
    cudaGetSymbolAddress((void**)&wvl, g_wvl);
    cudaGetSymbolAddress((void**)&woh, g_woh);
    cudaGetSymbolAddress((void**)&wol, g_wol);

    const int smem_gemm = 3 * STAGE_BYTES;   // 196608
    cudaFuncSetAttribute(gemm_mma<0>, cudaFuncAttributeMaxDynamicSharedMemorySize,
                         smem_gemm);
    cudaFuncSetAttribute(gemm_mma<1>, cudaFuncAttributeMaxDynamicSharedMemorySize,
                         smem_gemm);
    cudaFuncSetAttribute(flash_mma, cudaFuncAttributeMaxDynamicSharedMemorySize,
                         FA_SMEM);

    // weight split+transpose
    dim3 wsg(32, 32), wsb(32, 8);
    wsplit_t<<<wsg, wsb>>>(Wq, wqh, wql);
    wsplit_t<<<wsg, wsb>>>(Wk, wkh, wkl);
    wsplit_t<<<wsg, wsb>>>(Wv, wvh, wvl);
    wsplit_t<<<wsg, wsb>>>(Wo, woh, wol);

    // x split
    split_fp32<<<(MTOT * DD) / 1024, 256>>>((const float4*)x, (uint2*)xh, (uint2*)xl);

    dim3 gg(DD / 128, MTOT / 128);   // (8, 64)
    // QKV projections -> bf16 hi/lo (Q pre-scaled by 1/sqrt(hd)=0.125)
    gemm_mma<1><<<gg, 256, smem_gemm>>>(xh, xl, wqh, wql, bq, nullptr, qh, ql, 0.125f);
    gemm_mma<1><<<gg, 256, smem_gemm>>>(xh, xl, wkh, wkl, bk, nullptr, kh, kl, 1.0f);
    gemm_mma<1><<<gg, 256, smem_gemm>>>(xh, xl, wvh, wvl, bv, nullptr, vh, vl, 1.0f);

    // flash attention -> hi/lo into x-split buffers (reuse)
    flash_mma<<<dim3(NN / 128, BB * HH), 256, FA_SMEM>>>(qh, ql, kh, kl, vh, vl, xh, xl);

    // output projection -> fp32 out
    gemm_mma<0><<<gg, 256, smem_gemm>>>(xh, xl, woh, wol, bo, out, nullptr, nullptr, 1.0f);
}

// round 9
// speedup vs baseline: 3.2125x; 1.0498x over previous
#include <cuda_runtime.h>
#include <cuda_bf16.h>
#include <cstdint>

// Problem constants
#define BB   4
#define NN   2048
#define DD   1024
#define HH   16
#define HDD  64
#define MTOT (BB * NN)   // 8192

// ---------------- scratch (device globals: no allocations allowed) ----------
__device__ __align__(256) __nv_bfloat16 g_xhi[MTOT * DD];
__device__ __align__(256) __nv_bfloat16 g_xlo[MTOT * DD];
__device__ __align__(256) __nv_bfloat16 g_qh[MTOT * DD];
__device__ __align__(256) __nv_bfloat16 g_ql[MTOT * DD];
__device__ __align__(256) __nv_bfloat16 g_kh[MTOT * DD];
__device__ __align__(256) __nv_bfloat16 g_kl[MTOT * DD];
__device__ __align__(256) __nv_bfloat16 g_vh[MTOT * DD];
__device__ __align__(256) __nv_bfloat16 g_vl[MTOT * DD];
__device__ __align__(256) __nv_bfloat16 g_wqh[DD * DD];
__device__ __align__(256) __nv_bfloat16 g_wql[DD * DD];
__device__ __align__(256) __nv_bfloat16 g_wkh[DD * DD];
__device__ __align__(256) __nv_bfloat16 g_wkl[DD * DD];
__device__ __align__(256) __nv_bfloat16 g_wvh[DD * DD];
__device__ __align__(256) __nv_bfloat16 g_wvl[DD * DD];
__device__ __align__(256) __nv_bfloat16 g_woh[DD * DD];
__device__ __align__(256) __nv_bfloat16 g_wol[DD * DD];

// =====================  small PTX helpers (arch-portable)  ==================
__device__ __forceinline__ uint32_t smem_u32(const void* p) {
    uint32_t a;
    asm("{ .reg .u64 t; cvta.to.shared.u64 t, %1; cvt.u32.u64 %0, t; }"
        : "=r"(a) : "l"(p));
    return a;
}
__device__ __forceinline__ void cpa16(uint32_t dst, const void* src) {
    asm volatile("cp.async.cg.shared.global [%0], [%1], 16;\n"
                 :: "r"(dst), "l"(src));
}
__device__ __forceinline__ void cp_commit() {
    asm volatile("cp.async.commit_group;\n" ::: "memory");
}
__device__ __forceinline__ void cp_wait1() {
    asm volatile("cp.async.wait_group 1;\n" ::: "memory");
}
__device__ __forceinline__ void cp_wait0() {
    asm volatile("cp.async.wait_group 0;\n" ::: "memory");
}
__device__ __forceinline__ void ldsm4(uint32_t* r, uint32_t addr) {
    asm volatile("ldmatrix.sync.aligned.m8n8.x4.shared.b16 {%0,%1,%2,%3}, [%4];\n"
                 : "=r"(r[0]), "=r"(r[1]), "=r"(r[2]), "=r"(r[3]) : "r"(addr));
}
__device__ __forceinline__ void ldsm4t(uint32_t* r, uint32_t addr) {
    asm volatile("ldmatrix.sync.aligned.m8n8.x4.trans.shared.b16 {%0,%1,%2,%3}, [%4];\n"
                 : "=r"(r[0]), "=r"(r[1]), "=r"(r[2]), "=r"(r[3]) : "r"(addr));
}
__device__ __forceinline__ void mma16816(float* d, const uint32_t* a,
                                         uint32_t b0, uint32_t b1) {
    asm volatile(
        "mma.sync.aligned.m16n8k16.row.col.f32.bf16.bf16.f32 "
        "{%0,%1,%2,%3}, {%4,%5,%6,%7}, {%8,%9}, {%0,%1,%2,%3};\n"
        : "+f"(d[0]), "+f"(d[1]), "+f"(d[2]), "+f"(d[3])
        : "r"(a[0]), "r"(a[1]), "r"(a[2]), "r"(a[3]), "r"(b0), "r"(b1));
}
__device__ __forceinline__ uint32_t sw128(uint32_t off) {
    return off ^ ((off >> 3) & 0x70);
}
__device__ __forceinline__ void splitpack(float x, float y, uint32_t& h, uint32_t& l) {
    __nv_bfloat16 hx = __float2bfloat16(x);
    __nv_bfloat16 hy = __float2bfloat16(y);
    __nv_bfloat16 lx = __float2bfloat16(x - __bfloat162float(hx));
    __nv_bfloat16 ly = __float2bfloat16(y - __bfloat162float(hy));
    __nv_bfloat162 hv; hv.x = hx; hv.y = hy;
    __nv_bfloat162 lv; lv.x = lx; lv.y = ly;
    h = *reinterpret_cast<uint32_t*>(&hv);
    l = *reinterpret_cast<uint32_t*>(&lv);
}

// =====================  fp32 -> bf16 hi/lo split kernels  ===================
__global__ __launch_bounds__(256)
void split_fp32(const float4* __restrict__ in, uint2* __restrict__ hi,
                uint2* __restrict__ lo) {
    const int i = blockIdx.x * 256 + threadIdx.x;
    float4 v = in[i];
    __nv_bfloat16 h[4], l[4];
    float vv[4] = {v.x, v.y, v.z, v.w};
    #pragma unroll
    for (int j = 0; j < 4; j++) {
        h[j] = __float2bfloat16(vv[j]);
        l[j] = __float2bfloat16(vv[j] - __bfloat162float(h[j]));
    }
    hi[i] = *(const uint2*)h;
    lo[i] = *(const uint2*)l;
}

// All 4 weights in one launch: z selects (W, th, tl)
__global__ __launch_bounds__(256)
void wsplit_t4(const float* __restrict__ W0, const float* __restrict__ W1,
               const float* __restrict__ W2, const float* __restrict__ W3,
               __nv_bfloat16* __restrict__ t0h, __nv_bfloat16* __restrict__ t0l,
               __nv_bfloat16* __restrict__ t1h, __nv_bfloat16* __restrict__ t1l,
               __nv_bfloat16* __restrict__ t2h, __nv_bfloat16* __restrict__ t2l,
               __nv_bfloat16* __restrict__ t3h, __nv_bfloat16* __restrict__ t3l) {
    const int z = blockIdx.z;
    const float* W = (z == 0) ? W0 : (z == 1) ? W1 : (z == 2) ? W2 : W3;
    __nv_bfloat16* th = (z == 0) ? t0h : (z == 1) ? t1h : (z == 2) ? t2h : t3h;
    __nv_bfloat16* tl = (z == 0) ? t0l : (z == 1) ? t1l : (z == 2) ? t2l : t3l;

    __shared__ float t[32][33];
    const int n0 = blockIdx.x * 32, k0 = blockIdx.y * 32;
    const int tx = threadIdx.x, ty = threadIdx.y;   // (32,8)
    #pragma unroll
    for (int i = 0; i < 32; i += 8)
        t[ty + i][tx] = W[(size_t)(k0 + ty + i) * DD + n0 + tx];
    __syncthreads();
    #pragma unroll
    for (int i = 0; i < 32; i += 8) {
        const float v = t[tx][ty + i];
        const __nv_bfloat16 h = __float2bfloat16(v);
        const __nv_bfloat16 l = __float2bfloat16(v - __bfloat162float(h));
        const size_t o = (size_t)(n0 + ty + i) * DD + k0 + tx;
        th[o] = h; tl[o] = l;
    }
}

// ============  mma.sync split-bf16 GEMM core (device function)  =============
#define STAGE_BYTES 65536
#define OFF_AHI 0
#define OFF_ALO 16384
#define OFF_BHI 32768
#define OFF_BLO 49152
#define NCHUNK  16

template<int SPLIT>
__device__ __forceinline__
void gemm_body(const __nv_bfloat16* __restrict__ Ahi,
               const __nv_bfloat16* __restrict__ Alo,
               const __nv_bfloat16* __restrict__ Bhi,
               const __nv_bfloat16* __restrict__ Blo,
               const float* __restrict__ bias, float* __restrict__ C,
               __nv_bfloat16* __restrict__ Ch, __nv_bfloat16* __restrict__ Cl,
               float scale, int m0, int n0, char* smem) {
    const int tid = threadIdx.x;
    const int wid = tid >> 5, lane = tid & 31;
    const uint32_t sbase = smem_u32(smem);

    const __nv_bfloat16* pAhi = Ahi + (size_t)m0 * DD;
    const __nv_bfloat16* pAlo = Alo + (size_t)m0 * DD;
    const __nv_bfloat16* pBhi = Bhi + (size_t)n0 * DD;
    const __nv_bfloat16* pBlo = Blo + (size_t)n0 * DD;

    auto load_stage = [&](int stage, int ch) {
        const uint32_t sb = sbase + stage * STAGE_BYTES;
        const int coff = ch * 64;
        #pragma unroll
        for (int it = 0; it < 4; it++) {
            const int i = tid + it * 256;
            const int row = i >> 3, seg = i & 7;
            const uint32_t sw = sw128((uint32_t)(row * 128 + seg * 16));
            const size_t g = (size_t)row * DD + coff + seg * 8;
            cpa16(sb + OFF_AHI + sw, pAhi + g);
            cpa16(sb + OFF_ALO + sw, pAlo + g);
            cpa16(sb + OFF_BHI + sw, pBhi + g);
            cpa16(sb + OFF_BLO + sw, pBlo + g);
        }
        cp_commit();
    };

    const int wm = wid & 1, wn = wid >> 1;

    int a_row[4], b_row[2];
    #pragma unroll
    for (int i = 0; i < 4; i++)
        a_row[i] = wm * 64 + i * 16 + (lane & 7) + ((lane >> 3) & 1) * 8;
    #pragma unroll
    for (int j = 0; j < 2; j++)
        b_row[j] = wn * 32 + j * 16 + (lane & 7) + ((lane >> 4) & 1) * 8;
    const int cbA = lane >> 4;
    const int cbB = (lane >> 3) & 1;

    float acc[4][4][4];
    #pragma unroll
    for (int i = 0; i < 4; i++)
        #pragma unroll
        for (int j = 0; j < 4; j++)
            #pragma unroll
            for (int q = 0; q < 4; q++) acc[i][j][q] = 0.f;

    load_stage(0, 0);
    load_stage(1, 1);

    for (int c = 0; c < NCHUNK; c++) {
        if (c == NCHUNK - 1) cp_wait0(); else cp_wait1();
        __syncthreads();
        if (c + 2 < NCHUNK) load_stage((c + 2) % 3, c + 2);

        const uint32_t sb = sbase + (c % 3) * STAGE_BYTES;
        #pragma unroll
        for (int s = 0; s < 4; s++) {
            uint32_t ah[4][4], al[4][4], bh[2][4], bl[2][4];
            #pragma unroll
            for (int i = 0; i < 4; i++) {
                const uint32_t off = (uint32_t)(a_row[i] * 128) +
                    (uint32_t)(((2 * s + cbA) ^ (a_row[i] & 7)) << 4);
                ldsm4(ah[i], sb + OFF_AHI + off);
                ldsm4(al[i], sb + OFF_ALO + off);
            }
            #pragma unroll
            for (int j = 0; j < 2; j++) {
                const uint32_t off = (uint32_t)(b_row[j] * 128) +
                    (uint32_t)(((2 * s + cbB) ^ (b_row[j] & 7)) << 4);
                ldsm4(bh[j], sb + OFF_BHI + off);
                ldsm4(bl[j], sb + OFF_BLO + off);
            }
            #pragma unroll
            for (int i = 0; i < 4; i++)
                #pragma unroll
                for (int jj = 0; jj < 4; jj++)
                    mma16816(acc[i][jj], ah[i],
                             bh[jj >> 1][(jj & 1) * 2], bh[jj >> 1][(jj & 1) * 2 + 1]);
            #pragma unroll
            for (int i = 0; i < 4; i++)
                #pragma unroll
                for (int jj = 0; jj < 4; jj++)
                    mma16816(acc[i][jj], ah[i],
                             bl[jj >> 1][(jj & 1) * 2], bl[jj >> 1][(jj & 1) * 2 + 1]);
            #pragma unroll
            for (int i = 0; i < 4; i++)
                #pragma unroll
                for (int jj = 0; jj < 4; jj++)
                    mma16816(acc[i][jj], al[i],
                             bh[jj >> 1][(jj & 1) * 2], bh[jj >> 1][(jj & 1) * 2 + 1]);
        }
    }

    const int mbase = m0 + wm * 64 + (lane >> 2);
    const int nbase = n0 + wn * 32 + (lane & 3) * 2;
    #pragma unroll
    for (int jj = 0; jj < 4; jj++) {
        const int col = nbase + jj * 8;
        const float b0 = __ldg(&bias[col]);
        const float b1 = __ldg(&bias[col + 1]);
        #pragma unroll
        for (int i = 0; i < 4; i++) {
            const int r0 = mbase + i * 16;
            const float v0 = (acc[i][jj][0] + b0) * scale;
            const float v1 = (acc[i][jj][1] + b1) * scale;
            const float v2 = (acc[i][jj][2] + b0) * scale;
            const float v3 = (acc[i][jj][3] + b1) * scale;
            if (SPLIT) {
                uint32_t h0, l0, h1, l1;
                splitpack(v0, v1, h0, l0);
                splitpack(v2, v3, h1, l1);
                *(uint32_t*)(Ch + (size_t)r0 * DD + col) = h0;
                *(uint32_t*)(Cl + (size_t)r0 * DD + col) = l0;
                *(uint32_t*)(Ch + (size_t)(r0 + 8) * DD + col) = h1;
                *(uint32_t*)(Cl + (size_t)(r0 + 8) * DD + col) = l1;
            } else {
                *(float2*)(C + (size_t)r0 * DD + col) = make_float2(v0, v1);
                *(float2*)(C + (size_t)(r0 + 8) * DD + col) = make_float2(v2, v3);
            }
        }
    }
}

// Fused QKV: blockIdx.z selects weight/bias/output/scale
__global__ __launch_bounds__(256)
void gemm_qkv(const __nv_bfloat16* __restrict__ Ahi,
              const __nv_bfloat16* __restrict__ Alo,
              const __nv_bfloat16* __restrict__ Wqh, const __nv_bfloat16* __restrict__ Wql,
              const __nv_bfloat16* __restrict__ Wkh, const __nv_bfloat16* __restrict__ Wkl,
              const __nv_bfloat16* __restrict__ Wvh, const __nv_bfloat16* __restrict__ Wvl,
              const float* __restrict__ bq, const float* __restrict__ bk,
              const float* __restrict__ bv,
              __nv_bfloat16* __restrict__ Qh, __nv_bfloat16* __restrict__ Ql,
              __nv_bfloat16* __restrict__ Kh, __nv_bfloat16* __restrict__ Kl,
              __nv_bfloat16* __restrict__ Vh, __nv_bfloat16* __restrict__ Vl) {
    extern __shared__ __align__(1024) char smem[];
    const int z = blockIdx.z;
    const __nv_bfloat16* Bh = (z == 0) ? Wqh : (z == 1) ? Wkh : Wvh;
    const __nv_bfloat16* Bl = (z == 0) ? Wql : (z == 1) ? Wkl : Wvl;
    const float* bias = (z == 0) ? bq : (z == 1) ? bk : bv;
    __nv_bfloat16* Ch = (z == 0) ? Qh : (z == 1) ? Kh : Vh;
    __nv_bfloat16* Cl = (z == 0) ? Ql : (z == 1) ? Kl : Vl;
    const float scale = (z == 0) ? 0.125f : 1.0f;
    gemm_body<1>(Ahi, Alo, Bh, Bl, bias, nullptr, Ch, Cl, scale,
                 blockIdx.y * 128, blockIdx.x * 128, smem);
}

// Output projection: fp32 out
__global__ __launch_bounds__(256)
void gemm_out(const __nv_bfloat16* __restrict__ Ahi,
              const __nv_bfloat16* __restrict__ Alo,
              const __nv_bfloat16* __restrict__ Bhi,
              const __nv_bfloat16* __restrict__ Blo,
              const float* __restrict__ bias, float* __restrict__ C) {
    extern __shared__ __align__(1024) char smem[];
    gemm_body<0>(Ahi, Alo, Bhi, Blo, bias, C, nullptr, nullptr, 1.0f,
                 blockIdx.y * 128, blockIdx.x * 128, smem);
}

// ============  causal flash attention, split-bf16 mma.sync  =================
#define FQH 0
#define FQL 16384
#define FST0 32768
#define FSTG 32768
#define FS_KH 0
#define FS_KL 8192
#define FS_VH 16384
#define FS_VL 24576
#define FA_SMEM 98304

__global__ __launch_bounds__(256, 2)
void flash_mma(const __nv_bfloat16* __restrict__ Qh, const __nv_bfloat16* __restrict__ Ql,
               const __nv_bfloat16* __restrict__ Kh, const __nv_bfloat16* __restrict__ Kl,
               const __nv_bfloat16* __restrict__ Vh, const __nv_bfloat16* __restrict__ Vl,
               __nv_bfloat16* __restrict__ Oh, __nv_bfloat16* __restrict__ Ol) {
    extern __shared__ __align__(1024) char smem[];
    const uint32_t sb = smem_u32(smem);
    const int tid = threadIdx.x, wid = tid >> 5, lane = tid & 31;
    // heavy (high-qt) tiles first: CTAs dispatch roughly in bid order
    const int qt = gridDim.x - 1 - blockIdx.x;
    const int bh = blockIdx.y;
    const int b = bh >> 4, h = bh & 15;
    const int q0 = qt * 128;
    const size_t gbase = (size_t)b * NN * DD + h * HDD;

    {
        const __nv_bfloat16* qh = Qh + gbase + (size_t)q0 * DD;
        const __nv_bfloat16* ql = Ql + gbase + (size_t)q0 * DD;
        #pragma unroll
        for (int it = 0; it < 4; it++) {
            const int i = tid + it * 256;
            const int row = i >> 3, seg = i & 7;
            const uint32_t sw = sw128((uint32_t)(row * 128 + seg * 16));
            const size_t g = (size_t)row * DD + seg * 8;
            cpa16(sb + FQH + sw, qh + g);
            cpa16(sb + FQL + sw, ql + g);
        }
    }
    auto load_kv = [&](int stage, int kb) {
        const uint32_t s0 = sb + FST0 + stage * FSTG;
        const int k0 = kb * 64;
        #pragma unroll
        for (int it = 0; it < 2; it++) {
            const int i = tid + it * 256;
            const int row = i >> 3, seg = i & 7;
            const uint32_t sw = sw128((uint32_t)(row * 128 + seg * 16));
            const size_t g = gbase + (size_t)(k0 + row) * DD + seg * 8;
            cpa16(s0 + FS_KH + sw, Kh + g);
            cpa16(s0 + FS_KL + sw, Kl + g);
            cpa16(s0 + FS_VH + sw, Vh + g);
            cpa16(s0 + FS_VL + sw, Vl + g);
        }
        cp_commit();
    };
    load_kv(0, 0);

    float m0 = -1e30f, m1 = -1e30f, l0 = 0.f, l1 = 0.f;
    float oacc[8][4];
    #pragma unroll
    for (int j = 0; j < 8; j++)
        #pragma unroll
        for (int q = 0; q < 4; q++) oacc[j][q] = 0.f;

    const int nkb = 2 * qt + 2;
    for (int kb = 0; kb < nkb; kb++) {
        cp_wait0();
        __syncthreads();
        if (kb + 1 < nkb) load_kv((kb + 1) & 1, kb + 1);

        const int k0 = kb * 64;
        const bool active = (k0 <= q0 + wid * 16 + 15);
        if (active) {
            const uint32_t st = sb + FST0 + (kb & 1) * FSTG;

            float sacc[8][4];
            #pragma unroll
            for (int j = 0; j < 8; j++)
                #pragma unroll
                for (int q = 0; q < 4; q++) sacc[j][q] = 0.f;

            #pragma unroll
            for (int s = 0; s < 4; s++) {
                uint32_t ah[4], al[4];
                const int arow = wid * 16 + (lane & 15);
                const uint32_t aoff = sw128((uint32_t)(arow * 128 + (s * 2 + (lane >> 4)) * 16));
                ldsm4(ah, sb + FQH + aoff);
                ldsm4(al, sb + FQL + aoff);
                #pragma unroll
                for (int jg = 0; jg < 4; jg++) {
                    const int brow = jg * 16 + (lane & 7) + ((lane >> 4) & 1) * 8;
                    const uint32_t boff = sw128((uint32_t)(brow * 128 + (s * 2 + ((lane >> 3) & 1)) * 16));
                    uint32_t bh4[4], bl4[4];
                    ldsm4(bh4, st + FS_KH + boff);
                    ldsm4(bl4, st + FS_KL + boff);
                    mma16816(sacc[2 * jg],     ah, bh4[0], bh4[1]);
                    mma16816(sacc[2 * jg + 1], ah, bh4[2], bh4[3]);
                    mma16816(sacc[2 * jg],     ah, bl4[0], bl4[1]);
                    mma16816(sacc[2 * jg + 1], ah, bl4[2], bl4[3]);
                    mma16816(sacc[2 * jg],     al, bh4[0], bh4[1]);
                    mma16816(sacc[2 * jg + 1], al, bh4[2], bh4[3]);
                }
            }

            const int row0 = q0 + wid * 16 + (lane >> 2);
            if (k0 + 63 > q0 + wid * 16) {
                #pragma unroll
                for (int j = 0; j < 8; j++) {
                    const int c = k0 + j * 8 + (lane & 3) * 2;
                    if (c > row0)         sacc[j][0] = -1e30f;
                    if (c + 1 > row0)     sacc[j][1] = -1e30f;
                    if (c > row0 + 8)     sacc[j][2] = -1e30f;
                    if (c + 1 > row0 + 8) sacc[j][3] = -1e30f;
                }
            }

            float mx0 = -1e30f, mx1 = -1e30f;
            #pragma unroll
            for (int j = 0; j < 8; j++) {
                mx0 = fmaxf(mx0, fmaxf(sacc[j][0], sacc[j][1]));
                mx1 = fmaxf(mx1, fmaxf(sacc[j][2], sacc[j][3]));
            }
            mx0 = fmaxf(mx0, __shfl_xor_sync(0xffffffffu, mx0, 1));
            mx0 = fmaxf(mx0, __shfl_xor_sync(0xffffffffu, mx0, 2));
            mx1 = fmaxf(mx1, __shfl_xor_sync(0xffffffffu, mx1, 1));
            mx1 = fmaxf(mx1, __shfl_xor_sync(0xffffffffu, mx1, 2));
            const float m0n = fmaxf(m0, mx0), m1n = fmaxf(m1, mx1);
            const float a0 = __expf(m0 - m0n), a1 = __expf(m1 - m1n);
            m0 = m0n; m1 = m1n;
            float s0 = 0.f, s1 = 0.f;
            #pragma unroll
            for (int j = 0; j < 8; j++) {
                sacc[j][0] = __expf(sacc[j][0] - m0n);
                sacc[j][1] = __expf(sacc[j][1] - m0n);
                sacc[j][2] = __expf(sacc[j][2] - m1n);
                sacc[j][3] = __expf(sacc[j][3] - m1n);
                s0 += sacc[j][0] + sacc[j][1];
                s1 += sacc[j][2] + sacc[j][3];
            }
            s0 += __shfl_xor_sync(0xffffffffu, s0, 1);
            s0 += __shfl_xor_sync(0xffffffffu, s0, 2);
            s1 += __shfl_xor_sync(0xffffffffu, s1, 1);
            s1 += __shfl_xor_sync(0xffffffffu, s1, 2);
            l0 = l0 * a0 + s0;
            l1 = l1 * a1 + s1;
            #pragma unroll
            for (int j = 0; j < 8; j++) {
                oacc[j][0] *= a0; oacc[j][1] *= a0;
                oacc[j][2] *= a1; oacc[j][3] *= a1;
            }

            #pragma unroll
            for (int t = 0; t < 4; t++) {
                uint32_t pah[4], pal[4];
                splitpack(sacc[2 * t][0],     sacc[2 * t][1],     pah[0], pal[0]);
                splitpack(sacc[2 * t][2],     sacc[2 * t][3],     pah[1], pal[1]);
                splitpack(sacc[2 * t + 1][0], sacc[2 * t + 1][1], pah[2], pal[2]);
                splitpack(sacc[2 * t + 1][2], sacc[2 * t + 1][3], pah[3], pal[3]);
                const int jq = lane >> 3;
                const int vrow = t * 16 + (jq & 1) * 8 + (lane & 7);
                #pragma unroll
                for (int g = 0; g < 4; g++) {
                    const uint32_t voff = sw128((uint32_t)(vrow * 128 + (g * 16 + (jq >> 1) * 8) * 2));
                    uint32_t vh4[4], vl4[4];
                    ldsm4t(vh4, st + FS_VH + voff);
                    ldsm4t(vl4, st + FS_VL + voff);
                    mma16816(oacc[2 * g],     pah, vh4[0], vh4[1]);
                    mma16816(oacc[2 * g + 1], pah, vh4[2], vh4[3]);
                    mma16816(oacc[2 * g],     pah, vl4[0], vl4[1]);
                    mma16816(oacc[2 * g + 1], pah, vl4[2], vl4[3]);
                    mma16816(oacc[2 * g],     pal, vh4[0], vh4[1]);
                    mma16816(oacc[2 * g + 1], pal, vh4[2], vh4[3]);
                }
            }
        }
    }

    const float i0 = 1.f / l0, i1 = 1.f / l1;
    const size_t r0o = gbase + (size_t)(q0 + wid * 16 + (lane >> 2)) * DD;
    const size_t r1o = r0o + (size_t)8 * DD;
    #pragma unroll
    for (int j = 0; j < 8; j++) {
        const int c = j * 8 + (lane & 3) * 2;
        uint32_t h0, lo0, h1, lo1;
        splitpack(oacc[j][0] * i0, oacc[j][1] * i0, h0, lo0);
        splitpack(oacc[j][2] * i1, oacc[j][3] * i1, h1, lo1);
        *(uint32_t*)(Oh + r0o + c) = h0;
        *(uint32_t*)(Ol + r0o + c) = lo0;
        *(uint32_t*)(Oh + r1o + c) = h1;
        *(uint32_t*)(Ol + r1o + c) = lo1;
    }
}

// ---------------- launch ----------------------------------------------------
extern "C" void kernel_launch(void* const* d_in, const int* in_sizes, int n_in,
                              void* d_out, int out_size) {
    const float* x  = (const float*)d_in[0];
    const float* Wq = (const float*)d_in[1];
    const float* bq = (const float*)d_in[2];
    const float* Wk = (const float*)d_in[3];
    const float* bk = (const float*)d_in[4];
    const float* Wv = (const float*)d_in[5];
    const float* bv = (const float*)d_in[6];
    const float* Wo = (const float*)d_in[7];
    const float* bo = (const float*)d_in[8];
    float* out = (float*)d_out;

    __nv_bfloat16 *xh, *xl, *qh, *ql, *kh, *kl, *vh, *vl;
    __nv_bfloat16 *wqh, *wql, *wkh, *wkl, *wvh, *wvl, *woh, *wol;
    cudaGetSymbolAddress((void**)&xh, g_xhi);
    cudaGetSymbolAddress((void**)&xl, g_xlo);
    cudaGetSymbolAddress((void**)&qh, g_qh);
    cudaGetSymbolAddress((void**)&ql, g_ql);
    cudaGetSymbolAddress((void**)&kh, g_kh);
    cudaGetSymbolAddress((void**)&kl, g_kl);
    cudaGetSymbolAddress((void**)&vh, g_vh);
    cudaGetSymbolAddress((void**)&vl, g_vl);
    cudaGetSymbolAddress((void**)&wqh, g_wqh);
    cudaGetSymbolAddress((void**)&wql, g_wql);
    cudaGetSymbolAddress((void**)&wkh, g_wkh);
    cudaGetSymbolAddress((void**)&wkl, g_wkl);
    cudaGetSymbolAddress((void**)&wvh, g_wvh);
    cudaGetSymbolAddress((void**)&wvl, g_wvl);
    cudaGetSymbolAddress((void**)&woh, g_woh);
    cudaGetSymbolAddress((void**)&wol, g_wol);

    const int smem_gemm = 3 * STAGE_BYTES;   // 196608
    cudaFuncSetAttribute(gemm_qkv, cudaFuncAttributeMaxDynamicSharedMemorySize,
                         smem_gemm);
    cudaFuncSetAttribute(gemm_out, cudaFuncAttributeMaxDynamicSharedMemorySize,
                         smem_gemm);
    cudaFuncSetAttribute(flash_mma, cudaFuncAttributeMaxDynamicSharedMemorySize,
                         FA_SMEM);

    // weight split+transpose: all four in one launch
    wsplit_t4<<<dim3(32, 32, 4), dim3(32, 8)>>>(Wq, Wk, Wv, Wo,
                                                wqh, wql, wkh, wkl,
                                                wvh, wvl, woh, wol);

    // x split
    split_fp32<<<(MTOT * DD) / 1024, 256>>>((const float4*)x, (uint2*)xh, (uint2*)xl);

    // fused QKV projections (z = q/k/v; Q pre-scaled by 0.125)
    gemm_qkv<<<dim3(DD / 128, MTOT / 128, 3), 256, smem_gemm>>>(
        xh, xl, wqh, wql, wkh, wkl, wvh, wvl, bq, bk, bv,
        qh, ql, kh, kl, vh, vl);

    // flash attention -> hi/lo into x-split buffers (reuse)
    flash_mma<<<dim3(NN / 128, BB * HH), 256, FA_SMEM>>>(qh, ql, kh, kl, vh, vl, xh, xl);

    // output projection -> fp32 out
    gemm_out<<<dim3(DD / 128, MTOT / 128), 256, smem_gemm>>>(xh, xl, woh, wol, bo, out);
}

// round 11
// speedup vs baseline: 3.2262x; 1.0043x over previous
#include <cuda_runtime.h>
#include <cuda_bf16.h>
#include <cstdint>

// Problem constants
#define BB   4
#define NN   2048
#define DD   1024
#define HH   16
#define HDD  64
#define MTOT (BB * NN)   // 8192

// ---------------- scratch (device globals: no allocations allowed) ----------
__device__ __align__(256) __nv_bfloat16 g_xhi[MTOT * DD];
__device__ __align__(256) __nv_bfloat16 g_xlo[MTOT * DD];
__device__ __align__(256) __nv_bfloat16 g_qh[MTOT * DD];
__device__ __align__(256) __nv_bfloat16 g_ql[MTOT * DD];
__device__ __align__(256) __nv_bfloat16 g_kh[MTOT * DD];
__device__ __align__(256) __nv_bfloat16 g_kl[MTOT * DD];
__device__ __align__(256) __nv_bfloat16 g_vh[MTOT * DD];
__device__ __align__(256) __nv_bfloat16 g_vl[MTOT * DD];
__device__ __align__(256) __nv_bfloat16 g_wqh[DD * DD];
__device__ __align__(256) __nv_bfloat16 g_wql[DD * DD];
__device__ __align__(256) __nv_bfloat16 g_wkh[DD * DD];
__device__ __align__(256) __nv_bfloat16 g_wkl[DD * DD];
__device__ __align__(256) __nv_bfloat16 g_wvh[DD * DD];
__device__ __align__(256) __nv_bfloat16 g_wvl[DD * DD];
__device__ __align__(256) __nv_bfloat16 g_woh[DD * DD];
__device__ __align__(256) __nv_bfloat16 g_wol[DD * DD];

// =====================  small PTX helpers (arch-portable)  ==================
__device__ __forceinline__ uint32_t smem_u32(const void* p) {
    uint32_t a;
    asm("{ .reg .u64 t; cvta.to.shared.u64 t, %1; cvt.u32.u64 %0, t; }"
        : "=r"(a) : "l"(p));
    return a;
}
__device__ __forceinline__ void cpa16(uint32_t dst, const void* src) {
    asm volatile("cp.async.cg.shared.global [%0], [%1], 16;\n"
                 :: "r"(dst), "l"(src));
}
__device__ __forceinline__ void cp_commit() {
    asm volatile("cp.async.commit_group;\n" ::: "memory");
}
__device__ __forceinline__ void cp_wait1() {
    asm volatile("cp.async.wait_group 1;\n" ::: "memory");
}
__device__ __forceinline__ void cp_wait0() {
    asm volatile("cp.async.wait_group 0;\n" ::: "memory");
}
__device__ __forceinline__ void ldsm4(uint32_t* r, uint32_t addr) {
    asm volatile("ldmatrix.sync.aligned.m8n8.x4.shared.b16 {%0,%1,%2,%3}, [%4];\n"
                 : "=r"(r[0]), "=r"(r[1]), "=r"(r[2]), "=r"(r[3]) : "r"(addr));
}
__device__ __forceinline__ void ldsm4t(uint32_t* r, uint32_t addr) {
    asm volatile("ldmatrix.sync.aligned.m8n8.x4.trans.shared.b16 {%0,%1,%2,%3}, [%4];\n"
                 : "=r"(r[0]), "=r"(r[1]), "=r"(r[2]), "=r"(r[3]) : "r"(addr));
}
__device__ __forceinline__ void mma16816(float* d, const uint32_t* a,
                                         uint32_t b0, uint32_t b1) {
    asm volatile(
        "mma.sync.aligned.m16n8k16.row.col.f32.bf16.bf16.f32 "
        "{%0,%1,%2,%3}, {%4,%5,%6,%7}, {%8,%9}, {%0,%1,%2,%3};\n"
        : "+f"(d[0]), "+f"(d[1]), "+f"(d[2]), "+f"(d[3])
        : "r"(a[0]), "r"(a[1]), "r"(a[2]), "r"(a[3]), "r"(b0), "r"(b1));
}
__device__ __forceinline__ uint32_t sw128(uint32_t off) {
    return off ^ ((off >> 3) & 0x70);
}
__device__ __forceinline__ void splitpack(float x, float y, uint32_t& h, uint32_t& l) {
    __nv_bfloat16 hx = __float2bfloat16(x);
    __nv_bfloat16 hy = __float2bfloat16(y);
    __nv_bfloat16 lx = __float2bfloat16(x - __bfloat162float(hx));
    __nv_bfloat16 ly = __float2bfloat16(y - __bfloat162float(hy));
    __nv_bfloat162 hv; hv.x = hx; hv.y = hy;
    __nv_bfloat162 lv; lv.x = lx; lv.y = ly;
    h = *reinterpret_cast<uint32_t*>(&hv);
    l = *reinterpret_cast<uint32_t*>(&lv);
}

// =====================  fp32 -> bf16 hi/lo split kernels  ===================
__global__ __launch_bounds__(256)
void split_fp32(const float4* __restrict__ in, uint2* __restrict__ hi,
                uint2* __restrict__ lo) {
    const int i = blockIdx.x * 256 + threadIdx.x;
    float4 v = in[i];
    __nv_bfloat16 h[4], l[4];
    float vv[4] = {v.x, v.y, v.z, v.w};
    #pragma unroll
    for (int j = 0; j < 4; j++) {
        h[j] = __float2bfloat16(vv[j]);
        l[j] = __float2bfloat16(vv[j] - __bfloat162float(h[j]));
    }
    hi[i] = *(const uint2*)h;
    lo[i] = *(const uint2*)l;
}

// All 4 weights in one launch: z selects (W, th, tl)
__global__ __launch_bounds__(256)
void wsplit_t4(const float* __restrict__ W0, const float* __restrict__ W1,
               const float* __restrict__ W2, const float* __restrict__ W3,
               __nv_bfloat16* __restrict__ t0h, __nv_bfloat16* __restrict__ t0l,
               __nv_bfloat16* __restrict__ t1h, __nv_bfloat16* __restrict__ t1l,
               __nv_bfloat16* __restrict__ t2h, __nv_bfloat16* __restrict__ t2l,
               __nv_bfloat16* __restrict__ t3h, __nv_bfloat16* __restrict__ t3l) {
    const int z = blockIdx.z;
    const float* W = (z == 0) ? W0 : (z == 1) ? W1 : (z == 2) ? W2 : W3;
    __nv_bfloat16* th = (z == 0) ? t0h : (z == 1) ? t1h : (z == 2) ? t2h : t3h;
    __nv_bfloat16* tl = (z == 0) ? t0l : (z == 1) ? t1l : (z == 2) ? t2l : t3l;

    __shared__ float t[32][33];
    const int n0 = blockIdx.x * 32, k0 = blockIdx.y * 32;
    const int tx = threadIdx.x, ty = threadIdx.y;   // (32,8)
    #pragma unroll
    for (int i = 0; i < 32; i += 8)
        t[ty + i][tx] = W[(size_t)(k0 + ty + i) * DD + n0 + tx];
    __syncthreads();
    #pragma unroll
    for (int i = 0; i < 32; i += 8) {
        const float v = t[tx][ty + i];
        const __nv_bfloat16 h = __float2bfloat16(v);
        const __nv_bfloat16 l = __float2bfloat16(v - __bfloat162float(h));
        const size_t o = (size_t)(n0 + ty + i) * DD + k0 + tx;
        th[o] = h; tl[o] = l;
    }
}

// ============  mma.sync split-bf16 GEMM core (device function)  =============
// K-chunk 32; each 128B smem row packs [32 hi | 32 lo] bf16 (segs 0-3 hi,
// segs 4-7 lo). Stage = A 16KB + B 16KB = 32KB; 3 stages = 96KB -> 2 CTA/SM.
// Identical k16-step MMA ordering as the 64-chunk version (bitwise same).
#define STAGE_BYTES 32768
#define OFF_B 16384
#define NCHUNK  32

template<int SPLIT>
__device__ __forceinline__
void gemm_body(const __nv_bfloat16* __restrict__ Ahi,
               const __nv_bfloat16* __restrict__ Alo,
               const __nv_bfloat16* __restrict__ Bhi,
               const __nv_bfloat16* __restrict__ Blo,
               const float* __restrict__ bias, float* __restrict__ C,
               __nv_bfloat16* __restrict__ Ch, __nv_bfloat16* __restrict__ Cl,
               float scale, int m0, int n0, char* smem) {
    const int tid = threadIdx.x;
    const int wid = tid >> 5, lane = tid & 31;
    const uint32_t sbase = smem_u32(smem);

    const __nv_bfloat16* pAhi = Ahi + (size_t)m0 * DD;
    const __nv_bfloat16* pAlo = Alo + (size_t)m0 * DD;
    const __nv_bfloat16* pBhi = Bhi + (size_t)n0 * DD;
    const __nv_bfloat16* pBlo = Blo + (size_t)n0 * DD;

    // 2048 cpa16 per stage (A+B, hi+lo packed per row); 8 per thread.
    auto load_stage = [&](int stage, int ch) {
        const uint32_t sb = sbase + stage * STAGE_BYTES;
        const int coff = ch * 32;
        #pragma unroll
        for (int it = 0; it < 8; it++) {
            const int i = tid + it * 256;          // 0..2047
            const int op = i >> 10;                // 0 = A, 1 = B
            const int rem = i & 1023;
            const int row = rem >> 3, seg = rem & 7;
            const uint32_t dst = sb + (op << 14) +
                sw128((uint32_t)(row * 128 + seg * 16));
            const __nv_bfloat16* hi = op ? pBhi : pAhi;
            const __nv_bfloat16* lo = op ? pBlo : pAlo;
            const size_t g = (size_t)row * DD + coff + (seg & 3) * 8;
            cpa16(dst, ((seg < 4) ? hi : lo) + g);
        }
        cp_commit();
    };

    const int wm = wid & 1, wn = wid >> 1;

    int a_row[4], b_row[2];
    #pragma unroll
    for (int i = 0; i < 4; i++)
        a_row[i] = wm * 64 + i * 16 + (lane & 7) + ((lane >> 3) & 1) * 8;
    #pragma unroll
    for (int j = 0; j < 2; j++)
        b_row[j] = wn * 32 + j * 16 + (lane & 7) + ((lane >> 4) & 1) * 8;
    const int cbA = lane >> 4;
    const int cbB = (lane >> 3) & 1;

    float acc[4][4][4];
    #pragma unroll
    for (int i = 0; i < 4; i++)
        #pragma unroll
        for (int j = 0; j < 4; j++)
            #pragma unroll
            for (int q = 0; q < 4; q++) acc[i][j][q] = 0.f;

    load_stage(0, 0);
    load_stage(1, 1);

    for (int c = 0; c < NCHUNK; c++) {
        if (c == NCHUNK - 1) cp_wait0(); else cp_wait1();
        __syncthreads();
        if (c + 2 < NCHUNK) load_stage((c + 2) % 3, c + 2);

        const uint32_t sb = sbase + (c % 3) * STAGE_BYTES;
        #pragma unroll
        for (int s = 0; s < 2; s++) {   // two k16 steps per 32-elem chunk
            uint32_t ah[4][4], al[4][4], bh[2][4], bl[2][4];
            #pragma unroll
            for (int i = 0; i < 4; i++) {
                const uint32_t base = (uint32_t)(a_row[i] * 128);
                const int segh = 2 * s + cbA;
                ldsm4(ah[i], sb + base + (uint32_t)((segh ^ (a_row[i] & 7)) << 4));
                ldsm4(al[i], sb + base + (uint32_t)(((segh + 4) ^ (a_row[i] & 7)) << 4));
            }
            #pragma unroll
            for (int j = 0; j < 2; j++) {
                const uint32_t base = OFF_B + (uint32_t)(b_row[j] * 128);
                const int segh = 2 * s + cbB;
                ldsm4(bh[j], sb + base + (uint32_t)((segh ^ (b_row[j] & 7)) << 4));
                ldsm4(bl[j], sb + base + (uint32_t)(((segh + 4) ^ (b_row[j] & 7)) << 4));
            }
            #pragma unroll
            for (int i = 0; i < 4; i++)
                #pragma unroll
                for (int jj = 0; jj < 4; jj++)
                    mma16816(acc[i][jj], ah[i],
                             bh[jj >> 1][(jj & 1) * 2], bh[jj >> 1][(jj & 1) * 2 + 1]);
            #pragma unroll
            for (int i = 0; i < 4; i++)
                #pragma unroll
                for (int jj = 0; jj < 4; jj++)
                    mma16816(acc[i][jj], ah[i],
                             bl[jj >> 1][(jj & 1) * 2], bl[jj >> 1][(jj & 1) * 2 + 1]);
            #pragma unroll
            for (int i = 0; i < 4; i++)
                #pragma unroll
                for (int jj = 0; jj < 4; jj++)
                    mma16816(acc[i][jj], al[i],
                             bh[jj >> 1][(jj & 1) * 2], bh[jj >> 1][(jj & 1) * 2 + 1]);
        }
    }

    const int mbase = m0 + wm * 64 + (lane >> 2);
    const int nbase = n0 + wn * 32 + (lane & 3) * 2;
    #pragma unroll
    for (int jj = 0; jj < 4; jj++) {
        const int col = nbase + jj * 8;
        const float b0 = __ldg(&bias[col]);
        const float b1 = __ldg(&bias[col + 1]);
        #pragma unroll
        for (int i = 0; i < 4; i++) {
            const int r0 = mbase + i * 16;
            const float v0 = (acc[i][jj][0] + b0) * scale;
            const float v1 = (acc[i][jj][1] + b1) * scale;
            const float v2 = (acc[i][jj][2] + b0) * scale;
            const float v3 = (acc[i][jj][3] + b1) * scale;
            if (SPLIT) {
                uint32_t h0, l0, h1, l1;
                splitpack(v0, v1, h0, l0);
                splitpack(v2, v3, h1, l1);
                *(uint32_t*)(Ch + (size_t)r0 * DD + col) = h0;
                *(uint32_t*)(Cl + (size_t)r0 * DD + col) = l0;
                *(uint32_t*)(Ch + (size_t)(r0 + 8) * DD + col) = h1;
                *(uint32_t*)(Cl + (size_t)(r0 + 8) * DD + col) = l1;
            } else {
                *(float2*)(C + (size_t)r0 * DD + col) = make_float2(v0, v1);
                *(float2*)(C + (size_t)(r0 + 8) * DD + col) = make_float2(v2, v3);
            }
        }
    }
}

// Fused QKV: blockIdx.z selects weight/bias/output/scale
__global__ __launch_bounds__(256, 2)
void gemm_qkv(const __nv_bfloat16* __restrict__ Ahi,
              const __nv_bfloat16* __restrict__ Alo,
              const __nv_bfloat16* __restrict__ Wqh, const __nv_bfloat16* __restrict__ Wql,
              const __nv_bfloat16* __restrict__ Wkh, const __nv_bfloat16* __restrict__ Wkl,
              const __nv_bfloat16* __restrict__ Wvh, const __nv_bfloat16* __restrict__ Wvl,
              const float* __restrict__ bq, const float* __restrict__ bk,
              const float* __restrict__ bv,
              __nv_bfloat16* __restrict__ Qh, __nv_bfloat16* __restrict__ Ql,
              __nv_bfloat16* __restrict__ Kh, __nv_bfloat16* __restrict__ Kl,
              __nv_bfloat16* __restrict__ Vh, __nv_bfloat16* __restrict__ Vl) {
    extern __shared__ __align__(1024) char smem[];
    const int z = blockIdx.z;
    const __nv_bfloat16* Bh = (z == 0) ? Wqh : (z == 1) ? Wkh : Wvh;
    const __nv_bfloat16* Bl = (z == 0) ? Wql : (z == 1) ? Wkl : Wvl;
    const float* bias = (z == 0) ? bq : (z == 1) ? bk : bv;
    __nv_bfloat16* Ch = (z == 0) ? Qh : (z == 1) ? Kh : Vh;
    __nv_bfloat16* Cl = (z == 0) ? Ql : (z == 1) ? Kl : Vl;
    const float scale = (z == 0) ? 0.125f : 1.0f;
    gemm_body<1>(Ahi, Alo, Bh, Bl, bias, nullptr, Ch, Cl, scale,
                 blockIdx.y * 128, blockIdx.x * 128, smem);
}

// Output projection: fp32 out
__global__ __launch_bounds__(256, 2)
void gemm_out(const __nv_bfloat16* __restrict__ Ahi,
              const __nv_bfloat16* __restrict__ Alo,
              const __nv_bfloat16* __restrict__ Bhi,
              const __nv_bfloat16* __restrict__ Blo,
              const float* __restrict__ bias, float* __restrict__ C) {
    extern __shared__ __align__(1024) char smem[];
    gemm_body<0>(Ahi, Alo, Bhi, Blo, bias, C, nullptr, nullptr, 1.0f,
                 blockIdx.y * 128, blockIdx.x * 128, smem);
}

// ============  causal flash attention, split-bf16 mma.sync  =================
#define FQH 0
#define FQL 16384
#define FST0 32768
#define FSTG 32768
#define FS_KH 0
#define FS_KL 8192
#define FS_VH 16384
#define FS_VL 24576
#define FA_SMEM 98304

__global__ __launch_bounds__(256, 2)
void flash_mma(const __nv_bfloat16* __restrict__ Qh, const __nv_bfloat16* __restrict__ Ql,
               const __nv_bfloat16* __restrict__ Kh, const __nv_bfloat16* __restrict__ Kl,
               const __nv_bfloat16* __restrict__ Vh, const __nv_bfloat16* __restrict__ Vl,
               __nv_bfloat16* __restrict__ Oh, __nv_bfloat16* __restrict__ Ol) {
    extern __shared__ __align__(1024) char smem[];
    const uint32_t sb = smem_u32(smem);
    const int tid = threadIdx.x, wid = tid >> 5, lane = tid & 31;
    // heavy (high-qt) tiles first: CTAs dispatch roughly in bid order
    const int qt = gridDim.x - 1 - blockIdx.x;
    const int bh = blockIdx.y;
    const int b = bh >> 4, h = bh & 15;
    const int q0 = qt * 128;
    const size_t gbase = (size_t)b * NN * DD + h * HDD;

    {
        const __nv_bfloat16* qh = Qh + gbase + (size_t)q0 * DD;
        const __nv_bfloat16* ql = Ql + gbase + (size_t)q0 * DD;
        #pragma unroll
        for (int it = 0; it < 4; it++) {
            const int i = tid + it * 256;
            const int row = i >> 3, seg = i & 7;
            const uint32_t sw = sw128((uint32_t)(row * 128 + seg * 16));
            const size_t g = (size_t)row * DD + seg * 8;
            cpa16(sb + FQH + sw, qh + g);
            cpa16(sb + FQL + sw, ql + g);
        }
    }
    auto load_kv = [&](int stage, int kb) {
        const uint32_t s0 = sb + FST0 + stage * FSTG;
        const int k0 = kb * 64;
        #pragma unroll
        for (int it = 0; it < 2; it++) {
            const int i = tid + it * 256;
            const int row = i >> 3, seg = i & 7;
            const uint32_t sw = sw128((uint32_t)(row * 128 + seg * 16));
            const size_t g = gbase + (size_t)(k0 + row) * DD + seg * 8;
            cpa16(s0 + FS_KH + sw, Kh + g);
            cpa16(s0 + FS_KL + sw, Kl + g);
            cpa16(s0 + FS_VH + sw, Vh + g);
            cpa16(s0 + FS_VL + sw, Vl + g);
        }
        cp_commit();
    };
    load_kv(0, 0);

    float m0 = -1e30f, m1 = -1e30f, l0 = 0.f, l1 = 0.f;
    float oacc[8][4];
    #pragma unroll
    for (int j = 0; j < 8; j++)
        #pragma unroll
        for (int q = 0; q < 4; q++) oacc[j][q] = 0.f;

    const int nkb = 2 * qt + 2;
    for (int kb = 0; kb < nkb; kb++) {
        cp_wait0();
        __syncthreads();
        if (kb + 1 < nkb) load_kv((kb + 1) & 1, kb + 1);

        const int k0 = kb * 64;
        const bool active = (k0 <= q0 + wid * 16 + 15);
        if (active) {
            const uint32_t st = sb + FST0 + (kb & 1) * FSTG;

            float sacc[8][4];
            #pragma unroll
            for (int j = 0; j < 8; j++)
                #pragma unroll
                for (int q = 0; q < 4; q++) sacc[j][q] = 0.f;

            #pragma unroll
            for (int s = 0; s < 4; s++) {
                uint32_t ah[4], al[4];
                const int arow = wid * 16 + (lane & 15);
                const uint32_t aoff = sw128((uint32_t)(arow * 128 + (s * 2 + (lane >> 4)) * 16));
                ldsm4(ah, sb + FQH + aoff);
                ldsm4(al, sb + FQL + aoff);
                #pragma unroll
                for (int jg = 0; jg < 4; jg++) {
                    const int brow = jg * 16 + (lane & 7) + ((lane >> 4) & 1) * 8;
                    const uint32_t boff = sw128((uint32_t)(brow * 128 + (s * 2 + ((lane >> 3) & 1)) * 16));
                    uint32_t bh4[4], bl4[4];
                    ldsm4(bh4, st + FS_KH + boff);
                    ldsm4(bl4, st + FS_KL + boff);
                    mma16816(sacc[2 * jg],     ah, bh4[0], bh4[1]);
                    mma16816(sacc[2 * jg + 1], ah, bh4[2], bh4[3]);
                    mma16816(sacc[2 * jg],     ah, bl4[0], bl4[1]);
                    mma16816(sacc[2 * jg + 1], ah, bl4[2], bl4[3]);
                    mma16816(sacc[2 * jg],     al, bh4[0], bh4[1]);
                    mma16816(sacc[2 * jg + 1], al, bh4[2], bh4[3]);
                }
            }

            const int row0 = q0 + wid * 16 + (lane >> 2);
            if (k0 + 63 > q0 + wid * 16) {
                #pragma unroll
                for (int j = 0; j < 8; j++) {
                    const int c = k0 + j * 8 + (lane & 3) * 2;
                    if (c > row0)         sacc[j][0] = -1e30f;
                    if (c + 1 > row0)     sacc[j][1] = -1e30f;
                    if (c > row0 + 8)     sacc[j][2] = -1e30f;
                    if (c + 1 > row0 + 8) sacc[j][3] = -1e30f;
                }
            }

            float mx0 = -1e30f, mx1 = -1e30f;
            #pragma unroll
            for (int j = 0; j < 8; j++) {
                mx0 = fmaxf(mx0, fmaxf(sacc[j][0], sacc[j][1]));
                mx1 = fmaxf(mx1, fmaxf(sacc[j][2], sacc[j][3]));
            }
            mx0 = fmaxf(mx0, __shfl_xor_sync(0xffffffffu, mx0, 1));
            mx0 = fmaxf(mx0, __shfl_xor_sync(0xffffffffu, mx0, 2));
            mx1 = fmaxf(mx1, __shfl_xor_sync(0xffffffffu, mx1, 1));
            mx1 = fmaxf(mx1, __shfl_xor_sync(0xffffffffu, mx1, 2));
            const float m0n = fmaxf(m0, mx0), m1n = fmaxf(m1, mx1);
            const float a0 = __expf(m0 - m0n), a1 = __expf(m1 - m1n);
            m0 = m0n; m1 = m1n;
            float s0 = 0.f, s1 = 0.f;
            #pragma unroll
            for (int j = 0; j < 8; j++) {
                sacc[j][0] = __expf(sacc[j][0] - m0n);
                sacc[j][1] = __expf(sacc[j][1] - m0n);
                sacc[j][2] = __expf(sacc[j][2] - m1n);
                sacc[j][3] = __expf(sacc[j][3] - m1n);
                s0 += sacc[j][0] + sacc[j][1];
                s1 += sacc[j][2] + sacc[j][3];
            }
            s0 += __shfl_xor_sync(0xffffffffu, s0, 1);
            s0 += __shfl_xor_sync(0xffffffffu, s0, 2);
            s1 += __shfl_xor_sync(0xffffffffu, s1, 1);
            s1 += __shfl_xor_sync(0xffffffffu, s1, 2);
            l0 = l0 * a0 + s0;
            l1 = l1 * a1 + s1;
            #pragma unroll
            for (int j = 0; j < 8; j++) {
                oacc[j][0] *= a0; oacc[j][1] *= a0;
                oacc[j][2] *= a1; oacc[j][3] *= a1;
            }

            #pragma unroll
            for (int t = 0; t < 4; t++) {
                uint32_t pah[4], pal[4];
                splitpack(sacc[2 * t][0],     sacc[2 * t][1],     pah[0], pal[0]);
                splitpack(sacc[2 * t][2],     sacc[2 * t][3],     pah[1], pal[1]);
                splitpack(sacc[2 * t + 1][0], sacc[2 * t + 1][1], pah[2], pal[2]);
                splitpack(sacc[2 * t + 1][2], sacc[2 * t + 1][3], pah[3], pal[3]);
                const int jq = lane >> 3;
                const int vrow = t * 16 + (jq & 1) * 8 + (lane & 7);
                #pragma unroll
                for (int g = 0; g < 4; g++) {
                    const uint32_t voff = sw128((uint32_t)(vrow * 128 + (g * 16 + (jq >> 1) * 8) * 2));
                    uint32_t vh4[4], vl4[4];
                    ldsm4t(vh4, st + FS_VH + voff);
                    ldsm4t(vl4, st + FS_VL + voff);
                    mma16816(oacc[2 * g],     pah, vh4[0], vh4[1]);
                    mma16816(oacc[2 * g + 1], pah, vh4[2], vh4[3]);
                    mma16816(oacc[2 * g],     pah, vl4[0], vl4[1]);
                    mma16816(oacc[2 * g + 1], pah, vl4[2], vl4[3]);
                    mma16816(oacc[2 * g],     pal, vh4[0], vh4[1]);
                    mma16816(oacc[2 * g + 1], pal, vh4[2], vh4[3]);
                }
            }
        }
    }

    const float i0 = 1.f / l0, i1 = 1.f / l1;
    const size_t r0o = gbase + (size_t)(q0 + wid * 16 + (lane >> 2)) * DD;
    const size_t r1o = r0o + (size_t)8 * DD;
    #pragma unroll
    for (int j = 0; j < 8; j++) {
        const int c = j * 8 + (lane & 3) * 2;
        uint32_t h0, lo0, h1, lo1;
        splitpack(oacc[j][0] * i0, oacc[j][1] * i0, h0, lo0);
        splitpack(oacc[j][2] * i1, oacc[j][3] * i1, h1, lo1);
        *(uint32_t*)(Oh + r0o + c) = h0;
        *(uint32_t*)(Ol + r0o + c) = lo0;
        *(uint32_t*)(Oh + r1o + c) = h1;
        *(uint32_t*)(Ol + r1o + c) = lo1;
    }
}

// ---------------- launch ----------------------------------------------------
extern "C" void kernel_launch(void* const* d_in, const int* in_sizes, int n_in,
                              void* d_out, int out_size) {
    const float* x  = (const float*)d_in[0];
    const float* Wq = (const float*)d_in[1];
    const float* bq = (const float*)d_in[2];
    const float* Wk = (const float*)d_in[3];
    const float* bk = (const float*)d_in[4];
    const float* Wv = (const float*)d_in[5];
    const float* bv = (const float*)d_in[6];
    const float* Wo = (const float*)d_in[7];
    const float* bo = (const float*)d_in[8];
    float* out = (float*)d_out;

    __nv_bfloat16 *xh, *xl, *qh, *ql, *kh, *kl, *vh, *vl;
    __nv_bfloat16 *wqh, *wql, *wkh, *wkl, *wvh, *wvl, *woh, *wol;
    cudaGetSymbolAddress((void**)&xh, g_xhi);
    cudaGetSymbolAddress((void**)&xl, g_xlo);
    cudaGetSymbolAddress((void**)&qh, g_qh);
    cudaGetSymbolAddress((void**)&ql, g_ql);
    cudaGetSymbolAddress((void**)&kh, g_kh);
    cudaGetSymbolAddress((void**)&kl, g_kl);
    cudaGetSymbolAddress((void**)&vh, g_vh);
    cudaGetSymbolAddress((void**)&vl, g_vl);
    cudaGetSymbolAddress((void**)&wqh, g_wqh);
    cudaGetSymbolAddress((void**)&wql, g_wql);
    cudaGetSymbolAddress((void**)&wkh, g_wkh);
    cudaGetSymbolAddress((void**)&wkl, g_wkl);
    cudaGetSymbolAddress((void**)&wvh, g_wvh);
    cudaGetSymbolAddress((void**)&wvl, g_wvl);
    cudaGetSymbolAddress((void**)&woh, g_woh);
    cudaGetSymbolAddress((void**)&wol, g_wol);

    const int smem_gemm = 3 * STAGE_BYTES;   // 98304 -> 2 CTAs/SM
    cudaFuncSetAttribute(gemm_qkv, cudaFuncAttributeMaxDynamicSharedMemorySize,
                         smem_gemm);
    cudaFuncSetAttribute(gemm_out, cudaFuncAttributeMaxDynamicSharedMemorySize,
                         smem_gemm);
    cudaFuncSetAttribute(flash_mma, cudaFuncAttributeMaxDynamicSharedMemorySize,
                         FA_SMEM);

    // weight split+transpose: all four in one launch
    wsplit_t4<<<dim3(32, 32, 4), dim3(32, 8)>>>(Wq, Wk, Wv, Wo,
                                                wqh, wql, wkh, wkl,
                                                wvh, wvl, woh, wol);

    // x split
    split_fp32<<<(MTOT * DD) / 1024, 256>>>((const float4*)x, (uint2*)xh, (uint2*)xl);

    // fused QKV projections (z = q/k/v; Q pre-scaled by 0.125)
    gemm_qkv<<<dim3(DD / 128, MTOT / 128, 3), 256, smem_gemm>>>(
        xh, xl, wqh, wql, wkh, wkl, wvh, wvl, bq, bk, bv,
        qh, ql, kh, kl, vh, vl);

    // flash attention -> hi/lo into x-split buffers (reuse)
    flash_mma<<<dim3(NN / 128, BB * HH), 256, FA_SMEM>>>(qh, ql, kh, kl, vh, vl, xh, xl);

    // output projection -> fp32 out
    gemm_out<<<dim3(DD / 128, MTOT / 128), 256, smem_gemm>>>(xh, xl, woh, wol, bo, out);
}

// round 12
// speedup vs baseline: 3.7773x; 1.1708x over previous
#include <cuda_runtime.h>
#include <cuda_bf16.h>
#include <cuda_fp16.h>
#include <cstdint>

// Problem constants
#define BB   4
#define NN   2048
#define DD   1024
#define HH   16
#define HDD  64
#define MTOT (BB * NN)   // 8192

// ---------------- scratch (device globals: no allocations allowed) ----------
// fp16 activation buffer: holds x (pre-QKV) then attention output (pre-Wo)
__device__ __align__(256) __half g_xa[MTOT * DD];
// QKV projections, bf16 hi/lo (Q pre-scaled by 1/8) for 3-term flash
__device__ __align__(256) __nv_bfloat16 g_qh[MTOT * DD];
__device__ __align__(256) __nv_bfloat16 g_ql[MTOT * DD];
__device__ __align__(256) __nv_bfloat16 g_kh[MTOT * DD];
__device__ __align__(256) __nv_bfloat16 g_kl[MTOT * DD];
__device__ __align__(256) __nv_bfloat16 g_vh[MTOT * DD];
__device__ __align__(256) __nv_bfloat16 g_vl[MTOT * DD];
// transposed weight splits: [n][k] K-major, fp16 hi/lo (2-term split)
__device__ __align__(256) __half g_wqh[DD * DD];
__device__ __align__(256) __half g_wql[DD * DD];
__device__ __align__(256) __half g_wkh[DD * DD];
__device__ __align__(256) __half g_wkl[DD * DD];
__device__ __align__(256) __half g_wvh[DD * DD];
__device__ __align__(256) __half g_wvl[DD * DD];
__device__ __align__(256) __half g_woh[DD * DD];
__device__ __align__(256) __half g_wol[DD * DD];

// =====================  small PTX helpers (arch-portable)  ==================
__device__ __forceinline__ uint32_t smem_u32(const void* p) {
    uint32_t a;
    asm("{ .reg .u64 t; cvta.to.shared.u64 t, %1; cvt.u32.u64 %0, t; }"
        : "=r"(a) : "l"(p));
    return a;
}
__device__ __forceinline__ void cpa16(uint32_t dst, const void* src) {
    asm volatile("cp.async.cg.shared.global [%0], [%1], 16;\n"
                 :: "r"(dst), "l"(src));
}
__device__ __forceinline__ void cp_commit() {
    asm volatile("cp.async.commit_group;\n" ::: "memory");
}
__device__ __forceinline__ void cp_wait1() {
    asm volatile("cp.async.wait_group 1;\n" ::: "memory");
}
__device__ __forceinline__ void cp_wait0() {
    asm volatile("cp.async.wait_group 0;\n" ::: "memory");
}
__device__ __forceinline__ void ldsm4(uint32_t* r, uint32_t addr) {
    asm volatile("ldmatrix.sync.aligned.m8n8.x4.shared.b16 {%0,%1,%2,%3}, [%4];\n"
                 : "=r"(r[0]), "=r"(r[1]), "=r"(r[2]), "=r"(r[3]) : "r"(addr));
}
__device__ __forceinline__ void ldsm4t(uint32_t* r, uint32_t addr) {
    asm volatile("ldmatrix.sync.aligned.m8n8.x4.trans.shared.b16 {%0,%1,%2,%3}, [%4];\n"
                 : "=r"(r[0]), "=r"(r[1]), "=r"(r[2]), "=r"(r[3]) : "r"(addr));
}
// bf16 mma (flash)
__device__ __forceinline__ void mma16816(float* d, const uint32_t* a,
                                         uint32_t b0, uint32_t b1) {
    asm volatile(
        "mma.sync.aligned.m16n8k16.row.col.f32.bf16.bf16.f32 "
        "{%0,%1,%2,%3}, {%4,%5,%6,%7}, {%8,%9}, {%0,%1,%2,%3};\n"
        : "+f"(d[0]), "+f"(d[1]), "+f"(d[2]), "+f"(d[3])
        : "r"(a[0]), "r"(a[1]), "r"(a[2]), "r"(a[3]), "r"(b0), "r"(b1));
}
// fp16 mma (GEMMs)
__device__ __forceinline__ void mma16816h(float* d, const uint32_t* a,
                                          uint32_t b0, uint32_t b1) {
    asm volatile(
        "mma.sync.aligned.m16n8k16.row.col.f32.f16.f16.f32 "
        "{%0,%1,%2,%3}, {%4,%5,%6,%7}, {%8,%9}, {%0,%1,%2,%3};\n"
        : "+f"(d[0]), "+f"(d[1]), "+f"(d[2]), "+f"(d[3])
        : "r"(a[0]), "r"(a[1]), "r"(a[2]), "r"(a[3]), "r"(b0), "r"(b1));
}
__device__ __forceinline__ uint32_t sw128(uint32_t off) {
    return off ^ ((off >> 3) & 0x70);
}
__device__ __forceinline__ void splitpack(float x, float y, uint32_t& h, uint32_t& l) {
    __nv_bfloat16 hx = __float2bfloat16(x);
    __nv_bfloat16 hy = __float2bfloat16(y);
    __nv_bfloat16 lx = __float2bfloat16(x - __bfloat162float(hx));
    __nv_bfloat16 ly = __float2bfloat16(y - __bfloat162float(hy));
    __nv_bfloat162 hv; hv.x = hx; hv.y = hy;
    __nv_bfloat162 lv; lv.x = lx; lv.y = ly;
    h = *reinterpret_cast<uint32_t*>(&hv);
    l = *reinterpret_cast<uint32_t*>(&lv);
}

// =====================  prep kernels  =======================================
// fp32 -> single fp16 (activations)
__global__ __launch_bounds__(256)
void tohalf(const float4* __restrict__ in, uint2* __restrict__ out) {
    const int i = blockIdx.x * 256 + threadIdx.x;
    float4 v = in[i];
    __half2 a = __floats2half2_rn(v.x, v.y);
    __half2 b = __floats2half2_rn(v.z, v.w);
    out[i] = make_uint2(*reinterpret_cast<uint32_t*>(&a),
                        *reinterpret_cast<uint32_t*>(&b));
}

// W[k][n] -> Wt hi/lo fp16 [n][k]; all 4 weights in one launch (z selects)
__global__ __launch_bounds__(256)
void wsplit_t4(const float* __restrict__ W0, const float* __restrict__ W1,
               const float* __restrict__ W2, const float* __restrict__ W3,
               __half* __restrict__ t0h, __half* __restrict__ t0l,
               __half* __restrict__ t1h, __half* __restrict__ t1l,
               __half* __restrict__ t2h, __half* __restrict__ t2l,
               __half* __restrict__ t3h, __half* __restrict__ t3l) {
    const int z = blockIdx.z;
    const float* W = (z == 0) ? W0 : (z == 1) ? W1 : (z == 2) ? W2 : W3;
    __half* th = (z == 0) ? t0h : (z == 1) ? t1h : (z == 2) ? t2h : t3h;
    __half* tl = (z == 0) ? t0l : (z == 1) ? t1l : (z == 2) ? t2l : t3l;

    __shared__ float t[32][33];
    const int n0 = blockIdx.x * 32, k0 = blockIdx.y * 32;
    const int tx = threadIdx.x, ty = threadIdx.y;   // (32,8)
    #pragma unroll
    for (int i = 0; i < 32; i += 8)
        t[ty + i][tx] = W[(size_t)(k0 + ty + i) * DD + n0 + tx];
    __syncthreads();
    #pragma unroll
    for (int i = 0; i < 32; i += 8) {
        const float v = t[tx][ty + i];
        const __half h = __float2half(v);
        const __half l = __float2half(v - __half2float(h));
        const size_t o = (size_t)(n0 + ty + i) * DD + k0 + tx;
        th[o] = h; tl[o] = l;
    }
}

// ============  fp16 2-term GEMM core: C = (A@(Wh+Wl) + bias)*scale  =========
// A: [M][K] single fp16. B: [N][K] fp16 hi/lo (K-major rows).
// K-chunk 64 (128B rows), 3-stage cp.async ring.
#define STAGE_BYTES 49152
#define OFF_A   0
#define OFF_BHI 16384
#define OFF_BLO 32768
#define NCHUNK  16

template<int SPLIT>
__device__ __forceinline__
void gemm_body(const __half* __restrict__ A,
               const __half* __restrict__ Bhi,
               const __half* __restrict__ Blo,
               const float* __restrict__ bias, float* __restrict__ C,
               __nv_bfloat16* __restrict__ Ch, __nv_bfloat16* __restrict__ Cl,
               float scale, int m0, int n0, char* smem) {
    const int tid = threadIdx.x;
    const int wid = tid >> 5, lane = tid & 31;
    const uint32_t sbase = smem_u32(smem);

    const __half* pA   = A   + (size_t)m0 * DD;
    const __half* pBhi = Bhi + (size_t)n0 * DD;
    const __half* pBlo = Blo + (size_t)n0 * DD;

    // 3072 cpa16 per stage (A + Bhi + Blo); 12 per thread
    auto load_stage = [&](int stage, int ch) {
        const uint32_t sb = sbase + stage * STAGE_BYTES;
        const int coff = ch * 64;
        #pragma unroll
        for (int it = 0; it < 12; it++) {
            const int i = tid + it * 256;          // 0..3071
            const int op = i >> 10;                // 0=A, 1=Bhi, 2=Blo
            const int rem = i & 1023;
            const int row = rem >> 3, seg = rem & 7;
            const uint32_t dst = sb + (uint32_t)(op << 14) +
                sw128((uint32_t)(row * 128 + seg * 16));
            const __half* src = (op == 0) ? pA : (op == 1) ? pBhi : pBlo;
            cpa16(dst, src + (size_t)row * DD + coff + seg * 8);
        }
        cp_commit();
    };

    const int wm = wid & 1, wn = wid >> 1;

    int a_row[4], b_row[2];
    #pragma unroll
    for (int i = 0; i < 4; i++)
        a_row[i] = wm * 64 + i * 16 + (lane & 7) + ((lane >> 3) & 1) * 8;
    #pragma unroll
    for (int j = 0; j < 2; j++)
        b_row[j] = wn * 32 + j * 16 + (lane & 7) + ((lane >> 4) & 1) * 8;
    const int cbA = lane >> 4;
    const int cbB = (lane >> 3) & 1;

    float acc[4][4][4];
    #pragma unroll
    for (int i = 0; i < 4; i++)
        #pragma unroll
        for (int j = 0; j < 4; j++)
            #pragma unroll
            for (int q = 0; q < 4; q++) acc[i][j][q] = 0.f;

    load_stage(0, 0);
    load_stage(1, 1);

    for (int c = 0; c < NCHUNK; c++) {
        if (c == NCHUNK - 1) cp_wait0(); else cp_wait1();
        __syncthreads();
        if (c + 2 < NCHUNK) load_stage((c + 2) % 3, c + 2);

        const uint32_t sb = sbase + (c % 3) * STAGE_BYTES;
        #pragma unroll
        for (int s = 0; s < 4; s++) {   // four k16 steps per 64-elem chunk
            uint32_t a4[4][4], bh[2][4], bl[2][4];
            #pragma unroll
            for (int i = 0; i < 4; i++) {
                const uint32_t off = (uint32_t)(a_row[i] * 128) +
                    (uint32_t)(((2 * s + cbA) ^ (a_row[i] & 7)) << 4);
                ldsm4(a4[i], sb + OFF_A + off);
            }
            #pragma unroll
            for (int j = 0; j < 2; j++) {
                const uint32_t off = (uint32_t)(b_row[j] * 128) +
                    (uint32_t)(((2 * s + cbB) ^ (b_row[j] & 7)) << 4);
                ldsm4(bh[j], sb + OFF_BHI + off);
                ldsm4(bl[j], sb + OFF_BLO + off);
            }
            // term 1: A * W_hi
            #pragma unroll
            for (int i = 0; i < 4; i++)
                #pragma unroll
                for (int jj = 0; jj < 4; jj++)
                    mma16816h(acc[i][jj], a4[i],
                              bh[jj >> 1][(jj & 1) * 2], bh[jj >> 1][(jj & 1) * 2 + 1]);
            // term 2: A * W_lo
            #pragma unroll
            for (int i = 0; i < 4; i++)
                #pragma unroll
                for (int jj = 0; jj < 4; jj++)
                    mma16816h(acc[i][jj], a4[i],
                              bl[jj >> 1][(jj & 1) * 2], bl[jj >> 1][(jj & 1) * 2 + 1]);
        }
    }

    const int mbase = m0 + wm * 64 + (lane >> 2);
    const int nbase = n0 + wn * 32 + (lane & 3) * 2;
    #pragma unroll
    for (int jj = 0; jj < 4; jj++) {
        const int col = nbase + jj * 8;
        const float b0 = __ldg(&bias[col]);
        const float b1 = __ldg(&bias[col + 1]);
        #pragma unroll
        for (int i = 0; i < 4; i++) {
            const int r0 = mbase + i * 16;
            const float v0 = (acc[i][jj][0] + b0) * scale;
            const float v1 = (acc[i][jj][1] + b1) * scale;
            const float v2 = (acc[i][jj][2] + b0) * scale;
            const float v3 = (acc[i][jj][3] + b1) * scale;
            if (SPLIT) {
                uint32_t h0, l0, h1, l1;
                splitpack(v0, v1, h0, l0);
                splitpack(v2, v3, h1, l1);
                *(uint32_t*)(Ch + (size_t)r0 * DD + col) = h0;
                *(uint32_t*)(Cl + (size_t)r0 * DD + col) = l0;
                *(uint32_t*)(Ch + (size_t)(r0 + 8) * DD + col) = h1;
                *(uint32_t*)(Cl + (size_t)(r0 + 8) * DD + col) = l1;
            } else {
                *(float2*)(C + (size_t)r0 * DD + col) = make_float2(v0, v1);
                *(float2*)(C + (size_t)(r0 + 8) * DD + col) = make_float2(v2, v3);
            }
        }
    }
}

// Fused QKV: blockIdx.z selects weight/bias/output/scale
__global__ __launch_bounds__(256)
void gemm_qkv(const __half* __restrict__ A,
              const __half* __restrict__ Wqh, const __half* __restrict__ Wql,
              const __half* __restrict__ Wkh, const __half* __restrict__ Wkl,
              const __half* __restrict__ Wvh, const __half* __restrict__ Wvl,
              const float* __restrict__ bq, const float* __restrict__ bk,
              const float* __restrict__ bv,
              __nv_bfloat16* __restrict__ Qh, __nv_bfloat16* __restrict__ Ql,
              __nv_bfloat16* __restrict__ Kh, __nv_bfloat16* __restrict__ Kl,
              __nv_bfloat16* __restrict__ Vh, __nv_bfloat16* __restrict__ Vl) {
    extern __shared__ __align__(1024) char smem[];
    const int z = blockIdx.z;
    const __half* Bh = (z == 0) ? Wqh : (z == 1) ? Wkh : Wvh;
    const __half* Bl = (z == 0) ? Wql : (z == 1) ? Wkl : Wvl;
    const float* bias = (z == 0) ? bq : (z == 1) ? bk : bv;
    __nv_bfloat16* Ch = (z == 0) ? Qh : (z == 1) ? Kh : Vh;
    __nv_bfloat16* Cl = (z == 0) ? Ql : (z == 1) ? Kl : Vl;
    const float scale = (z == 0) ? 0.125f : 1.0f;
    gemm_body<1>(A, Bh, Bl, bias, nullptr, Ch, Cl, scale,
                 blockIdx.y * 128, blockIdx.x * 128, smem);
}

// Output projection: fp32 out
__global__ __launch_bounds__(256)
void gemm_out(const __half* __restrict__ A,
              const __half* __restrict__ Bhi,
              const __half* __restrict__ Blo,
              const float* __restrict__ bias, float* __restrict__ C) {
    extern __shared__ __align__(1024) char smem[];
    gemm_body<0>(A, Bhi, Blo, bias, C, nullptr, nullptr, 1.0f,
                 blockIdx.y * 128, blockIdx.x * 128, smem);
}

// ============  causal flash attention, split-bf16 mma.sync (3-term) ========
#define FQH 0
#define FQL 16384
#define FST0 32768
#define FSTG 32768
#define FS_KH 0
#define FS_KL 8192
#define FS_VH 16384
#define FS_VL 24576
#define FA_SMEM 98304

__global__ __launch_bounds__(256, 2)
void flash_mma(const __nv_bfloat16* __restrict__ Qh, const __nv_bfloat16* __restrict__ Ql,
               const __nv_bfloat16* __restrict__ Kh, const __nv_bfloat16* __restrict__ Kl,
               const __nv_bfloat16* __restrict__ Vh, const __nv_bfloat16* __restrict__ Vl,
               __half* __restrict__ O) {
    extern __shared__ __align__(1024) char smem[];
    const uint32_t sb = smem_u32(smem);
    const int tid = threadIdx.x, wid = tid >> 5, lane = tid & 31;
    // heavy (high-qt) tiles first: CTAs dispatch roughly in bid order
    const int qt = gridDim.x - 1 - blockIdx.x;
    const int bh = blockIdx.y;
    const int b = bh >> 4, h = bh & 15;
    const int q0 = qt * 128;
    const size_t gbase = (size_t)b * NN * DD + h * HDD;

    {
        const __nv_bfloat16* qh = Qh + gbase + (size_t)q0 * DD;
        const __nv_bfloat16* ql = Ql + gbase + (size_t)q0 * DD;
        #pragma unroll
        for (int it = 0; it < 4; it++) {
            const int i = tid + it * 256;
            const int row = i >> 3, seg = i & 7;
            const uint32_t sw = sw128((uint32_t)(row * 128 + seg * 16));
            const size_t g = (size_t)row * DD + seg * 8;
            cpa16(sb + FQH + sw, qh + g);
            cpa16(sb + FQL + sw, ql + g);
        }
    }
    auto load_kv = [&](int stage, int kb) {
        const uint32_t s0 = sb + FST0 + stage * FSTG;
        const int k0 = kb * 64;
        #pragma unroll
        for (int it = 0; it < 2; it++) {
            const int i = tid + it * 256;
            const int row = i >> 3, seg = i & 7;
            const uint32_t sw = sw128((uint32_t)(row * 128 + seg * 16));
            const size_t g = gbase + (size_t)(k0 + row) * DD + seg * 8;
            cpa16(s0 + FS_KH + sw, Kh + g);
            cpa16(s0 + FS_KL + sw, Kl + g);
            cpa16(s0 + FS_VH + sw, Vh + g);
            cpa16(s0 + FS_VL + sw, Vl + g);
        }
        cp_commit();
    };
    load_kv(0, 0);

    float m0 = -1e30f, m1 = -1e30f, l0 = 0.f, l1 = 0.f;
    float oacc[8][4];
    #pragma unroll
    for (int j = 0; j < 8; j++)
        #pragma unroll
        for (int q = 0; q < 4; q++) oacc[j][q] = 0.f;

    const int nkb = 2 * qt + 2;
    for (int kb = 0; kb < nkb; kb++) {
        cp_wait0();
        __syncthreads();
        if (kb + 1 < nkb) load_kv((kb + 1) & 1, kb + 1);

        const int k0 = kb * 64;
        const bool active = (k0 <= q0 + wid * 16 + 15);
        if (active) {
            const uint32_t st = sb + FST0 + (kb & 1) * FSTG;

            float sacc[8][4];
            #pragma unroll
            for (int j = 0; j < 8; j++)
                #pragma unroll
                for (int q = 0; q < 4; q++) sacc[j][q] = 0.f;

            #pragma unroll
            for (int s = 0; s < 4; s++) {
                uint32_t ah[4], al[4];
                const int arow = wid * 16 + (lane & 15);
                const uint32_t aoff = sw128((uint32_t)(arow * 128 + (s * 2 + (lane >> 4)) * 16));
                ldsm4(ah, sb + FQH + aoff);
                ldsm4(al, sb + FQL + aoff);
                #pragma unroll
                for (int jg = 0; jg < 4; jg++) {
                    const int brow = jg * 16 + (lane & 7) + ((lane >> 4) & 1) * 8;
                    const uint32_t boff = sw128((uint32_t)(brow * 128 + (s * 2 + ((lane >> 3) & 1)) * 16));
                    uint32_t bh4[4], bl4[4];
                    ldsm4(bh4, st + FS_KH + boff);
                    ldsm4(bl4, st + FS_KL + boff);
                    mma16816(sacc[2 * jg],     ah, bh4[0], bh4[1]);
                    mma16816(sacc[2 * jg + 1], ah, bh4[2], bh4[3]);
                    mma16816(sacc[2 * jg],     ah, bl4[0], bl4[1]);
                    mma16816(sacc[2 * jg + 1], ah, bl4[2], bl4[3]);
                    mma16816(sacc[2 * jg],     al, bh4[0], bh4[1]);
                    mma16816(sacc[2 * jg + 1], al, bh4[2], bh4[3]);
                }
            }

            const int row0 = q0 + wid * 16 + (lane >> 2);
            if (k0 + 63 > q0 + wid * 16) {
                #pragma unroll
                for (int j = 0; j < 8; j++) {
                    const int c = k0 + j * 8 + (lane & 3) * 2;
                    if (c > row0)         sacc[j][0] = -1e30f;
                    if (c + 1 > row0)     sacc[j][1] = -1e30f;
                    if (c > row0 + 8)     sacc[j][2] = -1e30f;
                    if (c + 1 > row0 + 8) sacc[j][3] = -1e30f;
                }
            }

            float mx0 = -1e30f, mx1 = -1e30f;
            #pragma unroll
            for (int j = 0; j < 8; j++) {
                mx0 = fmaxf(mx0, fmaxf(sacc[j][0], sacc[j][1]));
                mx1 = fmaxf(mx1, fmaxf(sacc[j][2], sacc[j][3]));
            }
            mx0 = fmaxf(mx0, __shfl_xor_sync(0xffffffffu, mx0, 1));
            mx0 = fmaxf(mx0, __shfl_xor_sync(0xffffffffu, mx0, 2));
            mx1 = fmaxf(mx1, __shfl_xor_sync(0xffffffffu, mx1, 1));
            mx1 = fmaxf(mx1, __shfl_xor_sync(0xffffffffu, mx1, 2));
            const float m0n = fmaxf(m0, mx0), m1n = fmaxf(m1, mx1);
            const float a0 = __expf(m0 - m0n), a1 = __expf(m1 - m1n);
            m0 = m0n; m1 = m1n;
            float s0 = 0.f, s1 = 0.f;
            #pragma unroll
            for (int j = 0; j < 8; j++) {
                sacc[j][0] = __expf(sacc[j][0] - m0n);
                sacc[j][1] = __expf(sacc[j][1] - m0n);
                sacc[j][2] = __expf(sacc[j][2] - m1n);
                sacc[j][3] = __expf(sacc[j][3] - m1n);
                s0 += sacc[j][0] + sacc[j][1];
                s1 += sacc[j][2] + sacc[j][3];
            }
            s0 += __shfl_xor_sync(0xffffffffu, s0, 1);
            s0 += __shfl_xor_sync(0xffffffffu, s0, 2);
            s1 += __shfl_xor_sync(0xffffffffu, s1, 1);
            s1 += __shfl_xor_sync(0xffffffffu, s1, 2);
            l0 = l0 * a0 + s0;
            l1 = l1 * a1 + s1;
            #pragma unroll
            for (int j = 0; j < 8; j++) {
                oacc[j][0] *= a0; oacc[j][1] *= a0;
                oacc[j][2] *= a1; oacc[j][3] *= a1;
            }

            #pragma unroll
            for (int t = 0; t < 4; t++) {
                uint32_t pah[4], pal[4];
                splitpack(sacc[2 * t][0],     sacc[2 * t][1],     pah[0], pal[0]);
                splitpack(sacc[2 * t][2],     sacc[2 * t][3],     pah[1], pal[1]);
                splitpack(sacc[2 * t + 1][0], sacc[2 * t + 1][1], pah[2], pal[2]);
                splitpack(sacc[2 * t + 1][2], sacc[2 * t + 1][3], pah[3], pal[3]);
                const int jq = lane >> 3;
                const int vrow = t * 16 + (jq & 1) * 8 + (lane & 7);
                #pragma unroll
                for (int g = 0; g < 4; g++) {
                    const uint32_t voff = sw128((uint32_t)(vrow * 128 + (g * 16 + (jq >> 1) * 8) * 2));
                    uint32_t vh4[4], vl4[4];
                    ldsm4t(vh4, st + FS_VH + voff);
                    ldsm4t(vl4, st + FS_VL + voff);
                    mma16816(oacc[2 * g],     pah, vh4[0], vh4[1]);
                    mma16816(oacc[2 * g + 1], pah, vh4[2], vh4[3]);
                    mma16816(oacc[2 * g],     pah, vl4[0], vl4[1]);
                    mma16816(oacc[2 * g + 1], pah, vl4[2], vl4[3]);
                    mma16816(oacc[2 * g],     pal, vh4[0], vh4[1]);
                    mma16816(oacc[2 * g + 1], pal, vh4[2], vh4[3]);
                }
            }
        }
    }

    // epilogue: normalize + single-fp16 output
    const float i0 = 1.f / l0, i1 = 1.f / l1;
    const size_t r0o = gbase + (size_t)(q0 + wid * 16 + (lane >> 2)) * DD;
    const size_t r1o = r0o + (size_t)8 * DD;
    #pragma unroll
    for (int j = 0; j < 8; j++) {
        const int c = j * 8 + (lane & 3) * 2;
        __half2 p0 = __floats2half2_rn(oacc[j][0] * i0, oacc[j][1] * i0);
        __half2 p1 = __floats2half2_rn(oacc[j][2] * i1, oacc[j][3] * i1);
        *(__half2*)(O + r0o + c) = p0;
        *(__half2*)(O + r1o + c) = p1;
    }
}

// ---------------- launch ----------------------------------------------------
extern "C" void kernel_launch(void* const* d_in, const int* in_sizes, int n_in,
                              void* d_out, int out_size) {
    const float* x  = (const float*)d_in[0];
    const float* Wq = (const float*)d_in[1];
    const float* bq = (const float*)d_in[2];
    const float* Wk = (const float*)d_in[3];
    const float* bk = (const float*)d_in[4];
    const float* Wv = (const float*)d_in[5];
    const float* bv = (const float*)d_in[6];
    const float* Wo = (const float*)d_in[7];
    const float* bo = (const float*)d_in[8];
    float* out = (float*)d_out;

    __half *xa, *wqh, *wql, *wkh, *wkl, *wvh, *wvl, *woh, *wol;
    __nv_bfloat16 *qh, *ql, *kh, *kl, *vh, *vl;
    cudaGetSymbolAddress((void**)&xa, g_xa);
    cudaGetSymbolAddress((void**)&qh, g_qh);
    cudaGetSymbolAddress((void**)&ql, g_ql);
    cudaGetSymbolAddress((void**)&kh, g_kh);
    cudaGetSymbolAddress((void**)&kl, g_kl);
    cudaGetSymbolAddress((void**)&vh, g_vh);
    cudaGetSymbolAddress((void**)&vl, g_vl);
    cudaGetSymbolAddress((void**)&wqh, g_wqh);
    cudaGetSymbolAddress((void**)&wql, g_wql);
    cudaGetSymbolAddress((void**)&wkh, g_wkh);
    cudaGetSymbolAddress((void**)&wkl, g_wkl);
    cudaGetSymbolAddress((void**)&wvh, g_wvh);
    cudaGetSymbolAddress((void**)&wvl, g_wvl);
    cudaGetSymbolAddress((void**)&woh, g_woh);
    cudaGetSymbolAddress((void**)&wol, g_wol);

    const int smem_gemm = 3 * STAGE_BYTES;   // 147456
    cudaFuncSetAttribute(gemm_qkv, cudaFuncAttributeMaxDynamicSharedMemorySize,
                         smem_gemm);
    cudaFuncSetAttribute(gemm_out, cudaFuncAttributeMaxDynamicSharedMemorySize,
                         smem_gemm);
    cudaFuncSetAttribute(flash_mma, cudaFuncAttributeMaxDynamicSharedMemorySize,
                         FA_SMEM);

    // weight split+transpose (fp16 hi/lo), all four in one launch
    wsplit_t4<<<dim3(32, 32, 4), dim3(32, 8)>>>(Wq, Wk, Wv, Wo,
                                                wqh, wql, wkh, wkl,
                                                wvh, wvl, woh, wol);

    // x -> single fp16
    tohalf<<<(MTOT * DD) / 1024, 256>>>((const float4*)x, (uint2*)xa);

    // fused QKV projections (z = q/k/v; Q pre-scaled by 0.125) -> bf16 hi/lo
    gemm_qkv<<<dim3(DD / 128, MTOT / 128, 3), 256, smem_gemm>>>(
        xa, wqh, wql, wkh, wkl, wvh, wvl, bq, bk, bv,
        qh, ql, kh, kl, vh, vl);

    // flash attention (3-term bf16) -> single fp16 into xa (x no longer needed)
    flash_mma<<<dim3(NN / 128, BB * HH), 256, FA_SMEM>>>(qh, ql, kh, kl, vh, vl, xa);

    // output projection -> fp32 out
    gemm_out<<<dim3(DD / 128, MTOT / 128), 256, smem_gemm>>>(xa, woh, wol, bo, out);
}

// round 14
// speedup vs baseline: 4.3817x; 1.1600x over previous
#include <cuda_runtime.h>
#include <cuda_bf16.h>
#include <cuda_fp16.h>
#include <cstdint>

// Problem constants
#define BB   4
#define NN   2048
#define DD   1024
#define HH   16
#define HDD  64
#define MTOT (BB * NN)   // 8192

// ---------------- scratch (device globals: no allocations allowed) ----------
// fp16 activation buffer: holds x (pre-QKV) then attention output (pre-Wo)
__device__ __align__(256) __half g_xa[MTOT * DD];
// Q: fp16 hi/lo (pre-scaled by 1/8).  K, V: single fp16.
__device__ __align__(256) __half g_qh[MTOT * DD];
__device__ __align__(256) __half g_ql[MTOT * DD];
__device__ __align__(256) __half g_k[MTOT * DD];
__device__ __align__(256) __half g_v[MTOT * DD];
// transposed weight splits: [n][k] K-major, fp16 hi/lo (2-term split)
__device__ __align__(256) __half g_wqh[DD * DD];
__device__ __align__(256) __half g_wql[DD * DD];
__device__ __align__(256) __half g_wkh[DD * DD];
__device__ __align__(256) __half g_wkl[DD * DD];
__device__ __align__(256) __half g_wvh[DD * DD];
__device__ __align__(256) __half g_wvl[DD * DD];
__device__ __align__(256) __half g_woh[DD * DD];
__device__ __align__(256) __half g_wol[DD * DD];

// =====================  small PTX helpers (arch-portable)  ==================
__device__ __forceinline__ uint32_t smem_u32(const void* p) {
    uint32_t a;
    asm("{ .reg .u64 t; cvta.to.shared.u64 t, %1; cvt.u32.u64 %0, t; }"
        : "=r"(a) : "l"(p));
    return a;
}
__device__ __forceinline__ void cpa16(uint32_t dst, const void* src) {
    asm volatile("cp.async.cg.shared.global [%0], [%1], 16;\n"
                 :: "r"(dst), "l"(src));
}
__device__ __forceinline__ void cp_commit() {
    asm volatile("cp.async.commit_group;\n" ::: "memory");
}
__device__ __forceinline__ void cp_wait1() {
    asm volatile("cp.async.wait_group 1;\n" ::: "memory");
}
__device__ __forceinline__ void cp_wait0() {
    asm volatile("cp.async.wait_group 0;\n" ::: "memory");
}
__device__ __forceinline__ void ldsm4(uint32_t* r, uint32_t addr) {
    asm volatile("ldmatrix.sync.aligned.m8n8.x4.shared.b16 {%0,%1,%2,%3}, [%4];\n"
                 : "=r"(r[0]), "=r"(r[1]), "=r"(r[2]), "=r"(r[3]) : "r"(addr));
}
__device__ __forceinline__ void ldsm4t(uint32_t* r, uint32_t addr) {
    asm volatile("ldmatrix.sync.aligned.m8n8.x4.trans.shared.b16 {%0,%1,%2,%3}, [%4];\n"
                 : "=r"(r[0]), "=r"(r[1]), "=r"(r[2]), "=r"(r[3]) : "r"(addr));
}
// fp16 mma, fp32 acc
__device__ __forceinline__ void mma16816h(float* d, const uint32_t* a,
                                          uint32_t b0, uint32_t b1) {
    asm volatile(
        "mma.sync.aligned.m16n8k16.row.col.f32.f16.f16.f32 "
        "{%0,%1,%2,%3}, {%4,%5,%6,%7}, {%8,%9}, {%0,%1,%2,%3};\n"
        : "+f"(d[0]), "+f"(d[1]), "+f"(d[2]), "+f"(d[3])
        : "r"(a[0]), "r"(a[1]), "r"(a[2]), "r"(a[3]), "r"(b0), "r"(b1));
}
__device__ __forceinline__ uint32_t sw128(uint32_t off) {
    return off ^ ((off >> 3) & 0x70);
}
// split (x,y) into packed fp16 hi and residual-lo pairs
__device__ __forceinline__ void splitpack_h(float x, float y, uint32_t& h, uint32_t& l) {
    __half hx = __float2half_rn(x);
    __half hy = __float2half_rn(y);
    __half lx = __float2half_rn(x - __half2float(hx));
    __half ly = __float2half_rn(y - __half2float(hy));
    __half2 hv; hv.x = hx; hv.y = hy;
    __half2 lv; lv.x = lx; lv.y = ly;
    h = *reinterpret_cast<uint32_t*>(&hv);
    l = *reinterpret_cast<uint32_t*>(&lv);
}

// =====================  prep kernels  =======================================
// fp32 -> single fp16 (activations)
__global__ __launch_bounds__(256)
void tohalf(const float4* __restrict__ in, uint2* __restrict__ out) {
    const int i = blockIdx.x * 256 + threadIdx.x;
    float4 v = in[i];
    __half2 a = __floats2half2_rn(v.x, v.y);
    __half2 b = __floats2half2_rn(v.z, v.w);
    out[i] = make_uint2(*reinterpret_cast<uint32_t*>(&a),
                        *reinterpret_cast<uint32_t*>(&b));
}

// W[k][n] -> Wt hi/lo fp16 [n][k]; all 4 weights in one launch (z selects)
__global__ __launch_bounds__(256)
void wsplit_t4(const float* __restrict__ W0, const float* __restrict__ W1,
               const float* __restrict__ W2, const float* __restrict__ W3,
               __half* __restrict__ t0h, __half* __restrict__ t0l,
               __half* __restrict__ t1h, __half* __restrict__ t1l,
               __half* __restrict__ t2h, __half* __restrict__ t2l,
               __half* __restrict__ t3h, __half* __restrict__ t3l) {
    const int z = blockIdx.z;
    const float* W = (z == 0) ? W0 : (z == 1) ? W1 : (z == 2) ? W2 : W3;
    __half* th = (z == 0) ? t0h : (z == 1) ? t1h : (z == 2) ? t2h : t3h;
    __half* tl = (z == 0) ? t0l : (z == 1) ? t1l : (z == 2) ? t2l : t3l;

    __shared__ float t[32][33];
    const int n0 = blockIdx.x * 32, k0 = blockIdx.y * 32;
    const int tx = threadIdx.x, ty = threadIdx.y;   // (32,8)
    #pragma unroll
    for (int i = 0; i < 32; i += 8)
        t[ty + i][tx] = W[(size_t)(k0 + ty + i) * DD + n0 + tx];
    __syncthreads();
    #pragma unroll
    for (int i = 0; i < 32; i += 8) {
        const float v = t[tx][ty + i];
        const __half h = __float2half_rn(v);
        const __half l = __float2half_rn(v - __half2float(h));
        const size_t o = (size_t)(n0 + ty + i) * DD + k0 + tx;
        th[o] = h; tl[o] = l;
    }
}

// ============  fp16 2-term GEMM core: C = (A@(Wh+Wl) + bias)*scale  =========
// A: [M][K] single fp16. B: [N][K] fp16 hi/lo (K-major rows).
// OUT: 0 = fp32 C;  1 = fp16 hi/lo (Ch,Cl);  2 = single fp16 (Ch).
#define STAGE_BYTES 49152
#define OFF_A   0
#define OFF_BHI 16384
#define OFF_BLO 32768
#define NCHUNK  16

template<int OUT>
__device__ __forceinline__
void gemm_body(const __half* __restrict__ A,
               const __half* __restrict__ Bhi,
               const __half* __restrict__ Blo,
               const float* __restrict__ bias, float* __restrict__ C,
               __half* __restrict__ Ch, __half* __restrict__ Cl,
               float scale, int m0, int n0, char* smem) {
    const int tid = threadIdx.x;
    const int wid = tid >> 5, lane = tid & 31;
    const uint32_t sbase = smem_u32(smem);

    const __half* pA   = A   + (size_t)m0 * DD;
    const __half* pBhi = Bhi + (size_t)n0 * DD;
    const __half* pBlo = Blo + (size_t)n0 * DD;

    // 3072 cpa16 per stage (A + Bhi + Blo); 12 per thread
    auto load_stage = [&](int stage, int ch) {
        const uint32_t sb = sbase + stage * STAGE_BYTES;
        const int coff = ch * 64;
        #pragma unroll
        for (int it = 0; it < 12; it++) {
            const int i = tid + it * 256;          // 0..3071
            const int op = i >> 10;                // 0=A, 1=Bhi, 2=Blo
            const int rem = i & 1023;
            const int row = rem >> 3, seg = rem & 7;
            const uint32_t dst = sb + (uint32_t)(op << 14) +
                sw128((uint32_t)(row * 128 + seg * 16));
            const __half* src = (op == 0) ? pA : (op == 1) ? pBhi : pBlo;
            cpa16(dst, src + (size_t)row * DD + coff + seg * 8);
        }
        cp_commit();
    };

    const int wm = wid & 1, wn = wid >> 1;

    int a_row[4], b_row[2];
    #pragma unroll
    for (int i = 0; i < 4; i++)
        a_row[i] = wm * 64 + i * 16 + (lane & 7) + ((lane >> 3) & 1) * 8;
    #pragma unroll
    for (int j = 0; j < 2; j++)
        b_row[j] = wn * 32 + j * 16 + (lane & 7) + ((lane >> 4) & 1) * 8;
    const int cbA = lane >> 4;
    const int cbB = (lane >> 3) & 1;

    float acc[4][4][4];
    #pragma unroll
    for (int i = 0; i < 4; i++)
        #pragma unroll
        for (int j = 0; j < 4; j++)
            #pragma unroll
            for (int q = 0; q < 4; q++) acc[i][j][q] = 0.f;

    load_stage(0, 0);
    load_stage(1, 1);

    for (int c = 0; c < NCHUNK; c++) {
        if (c == NCHUNK - 1) cp_wait0(); else cp_wait1();
        __syncthreads();
        if (c + 2 < NCHUNK) load_stage((c + 2) % 3, c + 2);

        const uint32_t sb = sbase + (c % 3) * STAGE_BYTES;
        #pragma unroll
        for (int s = 0; s < 4; s++) {   // four k16 steps per 64-elem chunk
            uint32_t a4[4][4], bh[2][4], bl[2][4];
            #pragma unroll
            for (int i = 0; i < 4; i++) {
                const uint32_t off = (uint32_t)(a_row[i] * 128) +
                    (uint32_t)(((2 * s + cbA) ^ (a_row[i] & 7)) << 4);
                ldsm4(a4[i], sb + OFF_A + off);
            }
            #pragma unroll
            for (int j = 0; j < 2; j++) {
                const uint32_t off = (uint32_t)(b_row[j] * 128) +
                    (uint32_t)(((2 * s + cbB) ^ (b_row[j] & 7)) << 4);
                ldsm4(bh[j], sb + OFF_BHI + off);
                ldsm4(bl[j], sb + OFF_BLO + off);
            }
            #pragma unroll
            for (int i = 0; i < 4; i++)
                #pragma unroll
                for (int jj = 0; jj < 4; jj++)
                    mma16816h(acc[i][jj], a4[i],
                              bh[jj >> 1][(jj & 1) * 2], bh[jj >> 1][(jj & 1) * 2 + 1]);
            #pragma unroll
            for (int i = 0; i < 4; i++)
                #pragma unroll
                for (int jj = 0; jj < 4; jj++)
                    mma16816h(acc[i][jj], a4[i],
                              bl[jj >> 1][(jj & 1) * 2], bl[jj >> 1][(jj & 1) * 2 + 1]);
        }
    }

    const int mbase = m0 + wm * 64 + (lane >> 2);
    const int nbase = n0 + wn * 32 + (lane & 3) * 2;
    #pragma unroll
    for (int jj = 0; jj < 4; jj++) {
        const int col = nbase + jj * 8;
        const float b0 = __ldg(&bias[col]);
        const float b1 = __ldg(&bias[col + 1]);
        #pragma unroll
        for (int i = 0; i < 4; i++) {
            const int r0 = mbase + i * 16;
            const float v0 = (acc[i][jj][0] + b0) * scale;
            const float v1 = (acc[i][jj][1] + b1) * scale;
            const float v2 = (acc[i][jj][2] + b0) * scale;
            const float v3 = (acc[i][jj][3] + b1) * scale;
            if (OUT == 1) {
                uint32_t h0, l0, h1, l1;
                splitpack_h(v0, v1, h0, l0);
                splitpack_h(v2, v3, h1, l1);
                *(uint32_t*)(Ch + (size_t)r0 * DD + col) = h0;
                *(uint32_t*)(Cl + (size_t)r0 * DD + col) = l0;
                *(uint32_t*)(Ch + (size_t)(r0 + 8) * DD + col) = h1;
                *(uint32_t*)(Cl + (size_t)(r0 + 8) * DD + col) = l1;
            } else if (OUT == 2) {
                __half2 p0 = __floats2half2_rn(v0, v1);
                __half2 p1 = __floats2half2_rn(v2, v3);
                *(__half2*)(Ch + (size_t)r0 * DD + col) = p0;
                *(__half2*)(Ch + (size_t)(r0 + 8) * DD + col) = p1;
            } else {
                *(float2*)(C + (size_t)r0 * DD + col) = make_float2(v0, v1);
                *(float2*)(C + (size_t)(r0 + 8) * DD + col) = make_float2(v2, v3);
            }
        }
    }
}

// Fused QKV: z=0 -> Q (fp16 hi/lo, scaled 0.125); z=1 -> K; z=2 -> V (single)
__global__ __launch_bounds__(256)
void gemm_qkv(const __half* __restrict__ A,
              const __half* __restrict__ Wqh, const __half* __restrict__ Wql,
              const __half* __restrict__ Wkh, const __half* __restrict__ Wkl,
              const __half* __restrict__ Wvh, const __half* __restrict__ Wvl,
              const float* __restrict__ bq, const float* __restrict__ bk,
              const float* __restrict__ bv,
              __half* __restrict__ Qh, __half* __restrict__ Ql,
              __half* __restrict__ K, __half* __restrict__ V) {
    extern __shared__ __align__(1024) char smem[];
    const int z = blockIdx.z;
    const int m0 = blockIdx.y * 128, n0 = blockIdx.x * 128;
    if (z == 0) {
        gemm_body<1>(A, Wqh, Wql, bq, nullptr, Qh, Ql, 0.125f, m0, n0, smem);
    } else if (z == 1) {
        gemm_body<2>(A, Wkh, Wkl, bk, nullptr, K, nullptr, 1.0f, m0, n0, smem);
    } else {
        gemm_body<2>(A, Wvh, Wvl, bv, nullptr, V, nullptr, 1.0f, m0, n0, smem);
    }
}

// Output projection: fp32 out
__global__ __launch_bounds__(256)
void gemm_out(const __half* __restrict__ A,
              const __half* __restrict__ Bhi,
              const __half* __restrict__ Blo,
              const float* __restrict__ bias, float* __restrict__ C) {
    extern __shared__ __align__(1024) char smem[];
    gemm_body<0>(A, Bhi, Blo, bias, C, nullptr, nullptr, 1.0f,
                 blockIdx.y * 128, blockIdx.x * 128, smem);
}

// ============  causal flash attention, 2-term fp16 mma.sync  ================
// S = (q_hi + q_lo) . k_single ; PV = (p_hi + p_lo) . v_single.
// Q fp16 hi/lo resident (32KB); K/V single fp16, 2-stage ring (16KB/stage).
#define FQH 0
#define FQL 16384
#define FST0 32768
#define FSTG 16384
#define FS_K 0
#define FS_V 8192
#define FA_SMEM 65536

__global__ __launch_bounds__(256, 2)
void flash_mma(const __half* __restrict__ Qh, const __half* __restrict__ Ql,
               const __half* __restrict__ K, const __half* __restrict__ V,
               __half* __restrict__ O) {
    extern __shared__ __align__(1024) char smem[];
    const uint32_t sb = smem_u32(smem);
    const int tid = threadIdx.x, wid = tid >> 5, lane = tid & 31;
    // heavy (high-qt) tiles first: CTAs dispatch roughly in bid order
    const int qt = gridDim.x - 1 - blockIdx.x;
    const int bh = blockIdx.y;
    const int b = bh >> 4, h = bh & 15;
    const int q0 = qt * 128;
    const size_t gbase = (size_t)b * NN * DD + h * HDD;

    // Q tile (hi+lo), 128 rows x 128B, swizzled
    {
        const __half* qh = Qh + gbase + (size_t)q0 * DD;
        const __half* ql = Ql + gbase + (size_t)q0 * DD;
        #pragma unroll
        for (int it = 0; it < 4; it++) {
            const int i = tid + it * 256;
            const int row = i >> 3, seg = i & 7;
            const uint32_t sw = sw128((uint32_t)(row * 128 + seg * 16));
            const size_t g = (size_t)row * DD + seg * 8;
            cpa16(sb + FQH + sw, qh + g);
            cpa16(sb + FQL + sw, ql + g);
        }
    }
    auto load_kv = [&](int stage, int kb) {
        const uint32_t s0 = sb + FST0 + stage * FSTG;
        const int k0 = kb * 64;
        #pragma unroll
        for (int it = 0; it < 2; it++) {
            const int i = tid + it * 256;     // 0..511
            const int row = i >> 3, seg = i & 7;
            const uint32_t sw = sw128((uint32_t)(row * 128 + seg * 16));
            const size_t g = gbase + (size_t)(k0 + row) * DD + seg * 8;
            cpa16(s0 + FS_K + sw, K + g);
            cpa16(s0 + FS_V + sw, V + g);
        }
        cp_commit();
    };
    load_kv(0, 0);

    float m0 = -1e30f, m1 = -1e30f, l0 = 0.f, l1 = 0.f;
    float oacc[8][4];
    #pragma unroll
    for (int j = 0; j < 8; j++)
        #pragma unroll
        for (int q = 0; q < 4; q++) oacc[j][q] = 0.f;

    const int nkb = 2 * qt + 2;
    for (int kb = 0; kb < nkb; kb++) {
        cp_wait0();
        __syncthreads();
        if (kb + 1 < nkb) load_kv((kb + 1) & 1, kb + 1);

        const int k0 = kb * 64;
        const bool active = (k0 <= q0 + wid * 16 + 15);
        if (active) {
            const uint32_t st = sb + FST0 + (kb & 1) * FSTG;

            // ---- S = Q K^T (2-term fp16) ----
            float sacc[8][4];
            #pragma unroll
            for (int j = 0; j < 8; j++)
                #pragma unroll
                for (int q = 0; q < 4; q++) sacc[j][q] = 0.f;

            #pragma unroll
            for (int s = 0; s < 4; s++) {
                uint32_t ah[4], al[4];
                const int arow = wid * 16 + (lane & 15);
                const uint32_t aoff = sw128((uint32_t)(arow * 128 + (s * 2 + (lane >> 4)) * 16));
                ldsm4(ah, sb + FQH + aoff);
                ldsm4(al, sb + FQL + aoff);
                #pragma unroll
                for (int jg = 0; jg < 4; jg++) {
                    const int brow = jg * 16 + (lane & 7) + ((lane >> 4) & 1) * 8;
                    const uint32_t boff = sw128((uint32_t)(brow * 128 + (s * 2 + ((lane >> 3) & 1)) * 16));
                    uint32_t k4[4];
                    ldsm4(k4, st + FS_K + boff);
                    mma16816h(sacc[2 * jg],     ah, k4[0], k4[1]);
                    mma16816h(sacc[2 * jg + 1], ah, k4[2], k4[3]);
                    mma16816h(sacc[2 * jg],     al, k4[0], k4[1]);
                    mma16816h(sacc[2 * jg + 1], al, k4[2], k4[3]);
                }
            }

            // ---- causal mask ----
            const int row0 = q0 + wid * 16 + (lane >> 2);
            if (k0 + 63 > q0 + wid * 16) {
                #pragma unroll
                for (int j = 0; j < 8; j++) {
                    const int c = k0 + j * 8 + (lane & 3) * 2;
                    if (c > row0)         sacc[j][0] = -1e30f;
                    if (c + 1 > row0)     sacc[j][1] = -1e30f;
                    if (c > row0 + 8)     sacc[j][2] = -1e30f;
                    if (c + 1 > row0 + 8) sacc[j][3] = -1e30f;
                }
            }

            // ---- online softmax ----
            float mx0 = -1e30f, mx1 = -1e30f;
            #pragma unroll
            for (int j = 0; j < 8; j++) {
                mx0 = fmaxf(mx0, fmaxf(sacc[j][0], sacc[j][1]));
                mx1 = fmaxf(mx1, fmaxf(sacc[j][2], sacc[j][3]));
            }
            mx0 = fmaxf(mx0, __shfl_xor_sync(0xffffffffu, mx0, 1));
            mx0 = fmaxf(mx0, __shfl_xor_sync(0xffffffffu, mx0, 2));
            mx1 = fmaxf(mx1, __shfl_xor_sync(0xffffffffu, mx1, 1));
            mx1 = fmaxf(mx1, __shfl_xor_sync(0xffffffffu, mx1, 2));
            const float m0n = fmaxf(m0, mx0), m1n = fmaxf(m1, mx1);
            const float a0 = __expf(m0 - m0n), a1 = __expf(m1 - m1n);
            m0 = m0n; m1 = m1n;
            float s0 = 0.f, s1 = 0.f;
            #pragma unroll
            for (int j = 0; j < 8; j++) {
                sacc[j][0] = __expf(sacc[j][0] - m0n);
                sacc[j][1] = __expf(sacc[j][1] - m0n);
                sacc[j][2] = __expf(sacc[j][2] - m1n);
                sacc[j][3] = __expf(sacc[j][3] - m1n);
                s0 += sacc[j][0] + sacc[j][1];
                s1 += sacc[j][2] + sacc[j][3];
            }
            s0 += __shfl_xor_sync(0xffffffffu, s0, 1);
            s0 += __shfl_xor_sync(0xffffffffu, s0, 2);
            s1 += __shfl_xor_sync(0xffffffffu, s1, 1);
            s1 += __shfl_xor_sync(0xffffffffu, s1, 2);
            l0 = l0 * a0 + s0;
            l1 = l1 * a1 + s1;
            #pragma unroll
            for (int j = 0; j < 8; j++) {
                oacc[j][0] *= a0; oacc[j][1] *= a0;
                oacc[j][2] *= a1; oacc[j][3] *= a1;
            }

            // ---- O += P @ V (2-term fp16: P split, V single) ----
            #pragma unroll
            for (int t = 0; t < 4; t++) {
                uint32_t pah[4], pal[4];
                splitpack_h(sacc[2 * t][0],     sacc[2 * t][1],     pah[0], pal[0]);
                splitpack_h(sacc[2 * t][2],     sacc[2 * t][3],     pah[1], pal[1]);
                splitpack_h(sacc[2 * t + 1][0], sacc[2 * t + 1][1], pah[2], pal[2]);
                splitpack_h(sacc[2 * t + 1][2], sacc[2 * t + 1][3], pah[3], pal[3]);
                const int jq = lane >> 3;
                const int vrow = t * 16 + (jq & 1) * 8 + (lane & 7);
                #pragma unroll
                for (int g = 0; g < 4; g++) {
                    const uint32_t voff = sw128((uint32_t)(vrow * 128 + (g * 16 + (jq >> 1) * 8) * 2));
                    uint32_t v4[4];
                    ldsm4t(v4, st + FS_V + voff);
                    mma16816h(oacc[2 * g],     pah, v4[0], v4[1]);
                    mma16816h(oacc[2 * g + 1], pah, v4[2], v4[3]);
                    mma16816h(oacc[2 * g],     pal, v4[0], v4[1]);
                    mma16816h(oacc[2 * g + 1], pal, v4[2], v4[3]);
                }
            }
        }
    }

    // epilogue: normalize + single-fp16 output
    const float i0 = 1.f / l0, i1 = 1.f / l1;
    const size_t r0o = gbase + (size_t)(q0 + wid * 16 + (lane >> 2)) * DD;
    const size_t r1o = r0o + (size_t)8 * DD;
    #pragma unroll
    for (int j = 0; j < 8; j++) {
        const int c = j * 8 + (lane & 3) * 2;
        __half2 p0 = __floats2half2_rn(oacc[j][0] * i0, oacc[j][1] * i0);
        __half2 p1 = __floats2half2_rn(oacc[j][2] * i1, oacc[j][3] * i1);
        *(__half2*)(O + r0o + c) = p0;
        *(__half2*)(O + r1o + c) = p1;
    }
}

// ---------------- launch ----------------------------------------------------
extern "C" void kernel_launch(void* const* d_in, const int* in_sizes, int n_in,
                              void* d_out, int out_size) {
    const float* x  = (const float*)d_in[0];
    const float* Wq = (const float*)d_in[1];
    const float* bq = (const float*)d_in[2];
    const float* Wk = (const float*)d_in[3];
    const float* bk = (const float*)d_in[4];
    const float* Wv = (const float*)d_in[5];
    const float* bv = (const float*)d_in[6];
    const float* Wo = (const float*)d_in[7];
    const float* bo = (const float*)d_in[8];
    float* out = (float*)d_out;

    __half *xa, *qh, *ql, *k, *v;
    __half *wqh, *wql, *wkh, *wkl, *wvh, *wvl, *woh, *wol;
    cudaGetSymbolAddress((void**)&xa, g_xa);
    cudaGetSymbolAddress((void**)&qh, g_qh);
    cudaGetSymbolAddress((void**)&ql, g_ql);
    cudaGetSymbolAddress((void**)&k, g_k);
    cudaGetSymbolAddress((void**)&v, g_v);
    cudaGetSymbolAddress((void**)&wqh, g_wqh);
    cudaGetSymbolAddress((void**)&wql, g_wql);
    cudaGetSymbolAddress((void**)&wkh, g_wkh);
    cudaGetSymbolAddress((void**)&wkl, g_wkl);
    cudaGetSymbolAddress((void**)&wvh, g_wvh);
    cudaGetSymbolAddress((void**)&wvl, g_wvl);
    cudaGetSymbolAddress((void**)&woh, g_woh);
    cudaGetSymbolAddress((void**)&wol, g_wol);

    const int smem_gemm = 3 * STAGE_BYTES;   // 147456
    cudaFuncSetAttribute(gemm_qkv, cudaFuncAttributeMaxDynamicSharedMemorySize,
                         smem_gemm);
    cudaFuncSetAttribute(gemm_out, cudaFuncAttributeMaxDynamicSharedMemorySize,
                         smem_gemm);
    cudaFuncSetAttribute(flash_mma, cudaFuncAttributeMaxDynamicSharedMemorySize,
                         FA_SMEM);

    // weight split+transpose (fp16 hi/lo), all four in one launch
    wsplit_t4<<<dim3(32, 32, 4), dim3(32, 8)>>>(Wq, Wk, Wv, Wo,
                                                wqh, wql, wkh, wkl,
                                                wvh, wvl, woh, wol);

    // x -> single fp16
    tohalf<<<(MTOT * DD) / 1024, 256>>>((const float4*)x, (uint2*)xa);

    // fused QKV projections: Q -> fp16 hi/lo (scaled 0.125); K,V -> single fp16
    gemm_qkv<<<dim3(DD / 128, MTOT / 128, 3), 256, smem_gemm>>>(
        xa, wqh, wql, wkh, wkl, wvh, wvl, bq, bk, bv, qh, ql, k, v);

    // flash attention (2-term fp16) -> single fp16 into xa (x no longer needed)
    flash_mma<<<dim3(NN / 128, BB * HH), 256, FA_SMEM>>>(qh, ql, k, v, xa);

    // output projection -> fp32 out
    gemm_out<<<dim3(DD / 128, MTOT / 128), 256, smem_gemm>>>(xa, woh, wol, bo, out);
}

// round 17
// speedup vs baseline: 5.1003x; 1.1640x over previous
#include <cuda_runtime.h>
#include <cuda_bf16.h>
#include <cuda_fp16.h>
#include <cstdint>

// Problem constants
#define BB   4
#define NN   2048
#define DD   1024
#define HH   16
#define HDD  64
#define MTOT (BB * NN)   // 8192

// ---------------- scratch (device globals: no allocations allowed) ----------
// fp16 activation buffer: holds x (pre-QKV) then attention output (pre-Wo)
__device__ __align__(256) __half g_xa[MTOT * DD];
// Q (pre-scaled by 1/8), K, V: single fp16
__device__ __align__(256) __half g_q[MTOT * DD];
__device__ __align__(256) __half g_k[MTOT * DD];
__device__ __align__(256) __half g_v[MTOT * DD];
// transposed weight splits: [n][k] K-major, fp16 hi/lo (2-term split)
__device__ __align__(256) __half g_wqh[DD * DD];
__device__ __align__(256) __half g_wql[DD * DD];
__device__ __align__(256) __half g_wkh[DD * DD];
__device__ __align__(256) __half g_wkl[DD * DD];
__device__ __align__(256) __half g_wvh[DD * DD];
__device__ __align__(256) __half g_wvl[DD * DD];
__device__ __align__(256) __half g_woh[DD * DD];
__device__ __align__(256) __half g_wol[DD * DD];

// =====================  small PTX helpers (arch-portable)  ==================
__device__ __forceinline__ uint32_t smem_u32(const void* p) {
    uint32_t a;
    asm("{ .reg .u64 t; cvta.to.shared.u64 t, %1; cvt.u32.u64 %0, t; }"
        : "=r"(a) : "l"(p));
    return a;
}
__device__ __forceinline__ void cpa16(uint32_t dst, const void* src) {
    asm volatile("cp.async.cg.shared.global [%0], [%1], 16;\n"
                 :: "r"(dst), "l"(src));
}
__device__ __forceinline__ void cp_commit() {
    asm volatile("cp.async.commit_group;\n" ::: "memory");
}
__device__ __forceinline__ void cp_wait1() {
    asm volatile("cp.async.wait_group 1;\n" ::: "memory");
}
__device__ __forceinline__ void cp_wait0() {
    asm volatile("cp.async.wait_group 0;\n" ::: "memory");
}
__device__ __forceinline__ void ldsm4(uint32_t* r, uint32_t addr) {
    asm volatile("ldmatrix.sync.aligned.m8n8.x4.shared.b16 {%0,%1,%2,%3}, [%4];\n"
                 : "=r"(r[0]), "=r"(r[1]), "=r"(r[2]), "=r"(r[3]) : "r"(addr));
}
__device__ __forceinline__ void ldsm4t(uint32_t* r, uint32_t addr) {
    asm volatile("ldmatrix.sync.aligned.m8n8.x4.trans.shared.b16 {%0,%1,%2,%3}, [%4];\n"
                 : "=r"(r[0]), "=r"(r[1]), "=r"(r[2]), "=r"(r[3]) : "r"(addr));
}
// fp16 mma, fp32 acc
__device__ __forceinline__ void mma16816h(float* d, const uint32_t* a,
                                          uint32_t b0, uint32_t b1) {
    asm volatile(
        "mma.sync.aligned.m16n8k16.row.col.f32.f16.f16.f32 "
        "{%0,%1,%2,%3}, {%4,%5,%6,%7}, {%8,%9}, {%0,%1,%2,%3};\n"
        : "+f"(d[0]), "+f"(d[1]), "+f"(d[2]), "+f"(d[3])
        : "r"(a[0]), "r"(a[1]), "r"(a[2]), "r"(a[3]), "r"(b0), "r"(b1));
}
__device__ __forceinline__ uint32_t sw128(uint32_t off) {
    return off ^ ((off >> 3) & 0x70);
}
// split (x,y) into packed fp16 hi and residual-lo pairs
__device__ __forceinline__ void splitpack_h(float x, float y, uint32_t& h, uint32_t& l) {
    __half hx = __float2half_rn(x);
    __half hy = __float2half_rn(y);
    __half lx = __float2half_rn(x - __half2float(hx));
    __half ly = __float2half_rn(y - __half2float(hy));
    __half2 hv; hv.x = hx; hv.y = hy;
    __half2 lv; lv.x = lx; lv.y = ly;
    h = *reinterpret_cast<uint32_t*>(&hv);
    l = *reinterpret_cast<uint32_t*>(&lv);
}
__device__ __forceinline__ uint32_t packh2(float x, float y) {
    __half2 p = __floats2half2_rn(x, y);
    return *reinterpret_cast<uint32_t*>(&p);
}

// =====================  prep kernels  =======================================
// fp32 -> single fp16 (activations)
__global__ __launch_bounds__(256)
void tohalf(const float4* __restrict__ in, uint2* __restrict__ out) {
    const int i = blockIdx.x * 256 + threadIdx.x;
    float4 v = in[i];
    __half2 a = __floats2half2_rn(v.x, v.y);
    __half2 b = __floats2half2_rn(v.z, v.w);
    out[i] = make_uint2(*reinterpret_cast<uint32_t*>(&a),
                        *reinterpret_cast<uint32_t*>(&b));
}

// W[k][n] -> Wt hi/lo fp16 [n][k]; all 4 weights in one launch (z selects)
__global__ __launch_bounds__(256)
void wsplit_t4(const float* __restrict__ W0, const float* __restrict__ W1,
               const float* __restrict__ W2, const float* __restrict__ W3,
               __half* __restrict__ t0h, __half* __restrict__ t0l,
               __half* __restrict__ t1h, __half* __restrict__ t1l,
               __half* __restrict__ t2h, __half* __restrict__ t2l,
               __half* __restrict__ t3h, __half* __restrict__ t3l) {
    const int z = blockIdx.z;
    const float* W = (z == 0) ? W0 : (z == 1) ? W1 : (z == 2) ? W2 : W3;
    __half* th = (z == 0) ? t0h : (z == 1) ? t1h : (z == 2) ? t2h : t3h;
    __half* tl = (z == 0) ? t0l : (z == 1) ? t1l : (z == 2) ? t2l : t3l;

    __shared__ float t[32][33];
    const int n0 = blockIdx.x * 32, k0 = blockIdx.y * 32;
    const int tx = threadIdx.x, ty = threadIdx.y;   // (32,8)
    #pragma unroll
    for (int i = 0; i < 32; i += 8)
        t[ty + i][tx] = W[(size_t)(k0 + ty + i) * DD + n0 + tx];
    __syncthreads();
    #pragma unroll
    for (int i = 0; i < 32; i += 8) {
        const float v = t[tx][ty + i];
        const __half h = __float2half_rn(v);
        const __half l = __float2half_rn(v - __half2float(h));
        const size_t o = (size_t)(n0 + ty + i) * DD + k0 + tx;
        th[o] = h; tl[o] = l;
    }
}

// ============  fp16 2-term GEMM core: C = (A@(Wh+Wl) + bias)*scale  =========
// A: [M][K] single fp16. B: [N][K] fp16 hi/lo (K-major rows).
// OUT: 0 = fp32 C;  2 = single fp16 (Ch).
#define STAGE_BYTES 49152
#define OFF_A   0
#define OFF_BHI 16384
#define OFF_BLO 32768
#define NCHUNK  16

template<int OUT>
__device__ __forceinline__
void gemm_body(const __half* __restrict__ A,
               const __half* __restrict__ Bhi,
               const __half* __restrict__ Blo,
               const float* __restrict__ bias, float* __restrict__ C,
               __half* __restrict__ Ch,
               float scale, int m0, int n0, char* smem) {
    const int tid = threadIdx.x;
    const int wid = tid >> 5, lane = tid & 31;
    const uint32_t sbase = smem_u32(smem);

    const __half* pA   = A   + (size_t)m0 * DD;
    const __half* pBhi = Bhi + (size_t)n0 * DD;
    const __half* pBlo = Blo + (size_t)n0 * DD;

    // 3072 cpa16 per stage (A + Bhi + Blo); 12 per thread
    auto load_stage = [&](int stage, int ch) {
        const uint32_t sb = sbase + stage * STAGE_BYTES;
        const int coff = ch * 64;
        #pragma unroll
        for (int it = 0; it < 12; it++) {
            const int i = tid + it * 256;          // 0..3071
            const int op = i >> 10;                // 0=A, 1=Bhi, 2=Blo
            const int rem = i & 1023;
            const int row = rem >> 3, seg = rem & 7;
            const uint32_t dst = sb + (uint32_t)(op << 14) +
                sw128((uint32_t)(row * 128 + seg * 16));
            const __half* src = (op == 0) ? pA : (op == 1) ? pBhi : pBlo;
            cpa16(dst, src + (size_t)row * DD + coff + seg * 8);
        }
        cp_commit();
    };

    const int wm = wid & 1, wn = wid >> 1;

    int a_row[4], b_row[2];
    #pragma unroll
    for (int i = 0; i < 4; i++)
        a_row[i] = wm * 64 + i * 16 + (lane & 7) + ((lane >> 3) & 1) * 8;
    #pragma unroll
    for (int j = 0; j < 2; j++)
        b_row[j] = wn * 32 + j * 16 + (lane & 7) + ((lane >> 4) & 1) * 8;
    const int cbA = lane >> 4;
    const int cbB = (lane >> 3) & 1;

    float acc[4][4][4];
    #pragma unroll
    for (int i = 0; i < 4; i++)
        #pragma unroll
        for (int j = 0; j < 4; j++)
            #pragma unroll
            for (int q = 0; q < 4; q++) acc[i][j][q] = 0.f;

    load_stage(0, 0);
    load_stage(1, 1);

    for (int c = 0; c < NCHUNK; c++) {
        if (c == NCHUNK - 1) cp_wait0(); else cp_wait1();
        __syncthreads();
        if (c + 2 < NCHUNK) load_stage((c + 2) % 3, c + 2);

        const uint32_t sb = sbase + (c % 3) * STAGE_BYTES;
        #pragma unroll
        for (int s = 0; s < 4; s++) {   // four k16 steps per 64-elem chunk
            uint32_t a4[4][4], bh[2][4], bl[2][4];
            #pragma unroll
            for (int i = 0; i < 4; i++) {
                const uint32_t off = (uint32_t)(a_row[i] * 128) +
                    (uint32_t)(((2 * s + cbA) ^ (a_row[i] & 7)) << 4);
                ldsm4(a4[i], sb + OFF_A + off);
            }
            #pragma unroll
            for (int j = 0; j < 2; j++) {
                const uint32_t off = (uint32_t)(b_row[j] * 128) +
                    (uint32_t)(((2 * s + cbB) ^ (b_row[j] & 7)) << 4);
                ldsm4(bh[j], sb + OFF_BHI + off);
                ldsm4(bl[j], sb + OFF_BLO + off);
            }
            #pragma unroll
            for (int i = 0; i < 4; i++)
                #pragma unroll
                for (int jj = 0; jj < 4; jj++)
                    mma16816h(acc[i][jj], a4[i],
                              bh[jj >> 1][(jj & 1) * 2], bh[jj >> 1][(jj & 1) * 2 + 1]);
            #pragma unroll
            for (int i = 0; i < 4; i++)
                #pragma unroll
                for (int jj = 0; jj < 4; jj++)
                    mma16816h(acc[i][jj], a4[i],
                              bl[jj >> 1][(jj & 1) * 2], bl[jj >> 1][(jj & 1) * 2 + 1]);
        }
    }

    const int mbase = m0 + wm * 64 + (lane >> 2);
    const int nbase = n0 + wn * 32 + (lane & 3) * 2;
    #pragma unroll
    for (int jj = 0; jj < 4; jj++) {
        const int col = nbase + jj * 8;
        const float b0 = __ldg(&bias[col]);
        const float b1 = __ldg(&bias[col + 1]);
        #pragma unroll
        for (int i = 0; i < 4; i++) {
            const int r0 = mbase + i * 16;
            const float v0 = (acc[i][jj][0] + b0) * scale;
            const float v1 = (acc[i][jj][1] + b1) * scale;
            const float v2 = (acc[i][jj][2] + b0) * scale;
            const float v3 = (acc[i][jj][3] + b1) * scale;
            if (OUT == 2) {
                *(uint32_t*)(Ch + (size_t)r0 * DD + col) = packh2(v0, v1);
                *(uint32_t*)(Ch + (size_t)(r0 + 8) * DD + col) = packh2(v2, v3);
            } else {
                *(float2*)(C + (size_t)r0 * DD + col) = make_float2(v0, v1);
                *(float2*)(C + (size_t)(r0 + 8) * DD + col) = make_float2(v2, v3);
            }
        }
    }
}

// Fused QKV: z selects weight/bias/output; all single-fp16 outputs
__global__ __launch_bounds__(256)
void gemm_qkv(const __half* __restrict__ A,
              const __half* __restrict__ Wqh, const __half* __restrict__ Wql,
              const __half* __restrict__ Wkh, const __half* __restrict__ Wkl,
              const __half* __restrict__ Wvh, const __half* __restrict__ Wvl,
              const float* __restrict__ bq, const float* __restrict__ bk,
              const float* __restrict__ bv,
              __half* __restrict__ Q, __half* __restrict__ K,
              __half* __restrict__ V) {
    extern __shared__ __align__(1024) char smem[];
    const int z = blockIdx.z;
    const __half* Bh = (z == 0) ? Wqh : (z == 1) ? Wkh : Wvh;
    const __half* Bl = (z == 0) ? Wql : (z == 1) ? Wkl : Wvl;
    const float* bias = (z == 0) ? bq : (z == 1) ? bk : bv;
    __half* Ch = (z == 0) ? Q : (z == 1) ? K : V;
    const float scale = (z == 0) ? 0.125f : 1.0f;
    gemm_body<2>(A, Bh, Bl, bias, nullptr, Ch, scale,
                 blockIdx.y * 128, blockIdx.x * 128, smem);
}

// Output projection: fp32 out
__global__ __launch_bounds__(256)
void gemm_out(const __half* __restrict__ A,
              const __half* __restrict__ Bhi,
              const __half* __restrict__ Blo,
              const float* __restrict__ bias, float* __restrict__ C) {
    extern __shared__ __align__(1024) char smem[];
    gemm_body<0>(A, Bhi, Blo, bias, C, nullptr, 1.0f,
                 blockIdx.y * 128, blockIdx.x * 128, smem);
}

// ============  causal flash attention, single-fp16 mma.sync  ================
// S = q . k ; PV = p . v — all single fp16 (fp32 accumulate).
// Q resident (16KB); K/V single fp16, 2-stage ring (16KB/stage) -> 48KB.
#define FQ   0
#define FST0 16384
#define FSTG 16384
#define FS_K 0
#define FS_V 8192
#define FA_SMEM 49152

__global__ __launch_bounds__(256, 2)
void flash_mma(const __half* __restrict__ Q, const __half* __restrict__ K,
               const __half* __restrict__ V, __half* __restrict__ O) {
    extern __shared__ __align__(1024) char smem[];
    const uint32_t sb = smem_u32(smem);
    const int tid = threadIdx.x, wid = tid >> 5, lane = tid & 31;
    // heavy (high-qt) tiles first: CTAs dispatch roughly in bid order
    const int qt = gridDim.x - 1 - blockIdx.x;
    const int bh = blockIdx.y;
    const int b = bh >> 4, h = bh & 15;
    const int q0 = qt * 128;
    const size_t gbase = (size_t)b * NN * DD + h * HDD;

    // Q tile, 128 rows x 128B, swizzled
    {
        const __half* qp = Q + gbase + (size_t)q0 * DD;
        #pragma unroll
        for (int it = 0; it < 4; it++) {
            const int i = tid + it * 256;
            const int row = i >> 3, seg = i & 7;
            const uint32_t sw = sw128((uint32_t)(row * 128 + seg * 16));
            cpa16(sb + FQ + sw, qp + (size_t)row * DD + seg * 8);
        }
    }
    auto load_kv = [&](int stage, int kb) {
        const uint32_t s0 = sb + FST0 + stage * FSTG;
        const int k0 = kb * 64;
        #pragma unroll
        for (int it = 0; it < 2; it++) {
            const int i = tid + it * 256;     // 0..511
            const int row = i >> 3, seg = i & 7;
            const uint32_t sw = sw128((uint32_t)(row * 128 + seg * 16));
            const size_t g = gbase + (size_t)(k0 + row) * DD + seg * 8;
            cpa16(s0 + FS_K + sw, K + g);
            cpa16(s0 + FS_V + sw, V + g);
        }
        cp_commit();
    };
    load_kv(0, 0);

    float m0 = -1e30f, m1 = -1e30f, l0 = 0.f, l1 = 0.f;
    float oacc[8][4];
    #pragma unroll
    for (int j = 0; j < 8; j++)
        #pragma unroll
        for (int q = 0; q < 4; q++) oacc[j][q] = 0.f;

    const int nkb = 2 * qt + 2;
    for (int kb = 0; kb < nkb; kb++) {
        cp_wait0();
        __syncthreads();
        if (kb + 1 < nkb) load_kv((kb + 1) & 1, kb + 1);

        const int k0 = kb * 64;
        const bool active = (k0 <= q0 + wid * 16 + 15);
        if (active) {
            const uint32_t st = sb + FST0 + (kb & 1) * FSTG;

            // ---- S = Q K^T (single fp16) ----
            float sacc[8][4];
            #pragma unroll
            for (int j = 0; j < 8; j++)
                #pragma unroll
                for (int q = 0; q < 4; q++) sacc[j][q] = 0.f;

            #pragma unroll
            for (int s = 0; s < 4; s++) {
                uint32_t a4[4];
                const int arow = wid * 16 + (lane & 15);
                const uint32_t aoff = sw128((uint32_t)(arow * 128 + (s * 2 + (lane >> 4)) * 16));
                ldsm4(a4, sb + FQ + aoff);
                #pragma unroll
                for (int jg = 0; jg < 4; jg++) {
                    const int brow = jg * 16 + (lane & 7) + ((lane >> 4) & 1) * 8;
                    const uint32_t boff = sw128((uint32_t)(brow * 128 + (s * 2 + ((lane >> 3) & 1)) * 16));
                    uint32_t k4[4];
                    ldsm4(k4, st + FS_K + boff);
                    mma16816h(sacc[2 * jg],     a4, k4[0], k4[1]);
                    mma16816h(sacc[2 * jg + 1], a4, k4[2], k4[3]);
                }
            }

            // ---- causal mask ----
            const int row0 = q0 + wid * 16 + (lane >> 2);
            if (k0 + 63 > q0 + wid * 16) {
                #pragma unroll
                for (int j = 0; j < 8; j++) {
                    const int c = k0 + j * 8 + (lane & 3) * 2;
                    if (c > row0)         sacc[j][0] = -1e30f;
                    if (c + 1 > row0)     sacc[j][1] = -1e30f;
                    if (c > row0 + 8)     sacc[j][2] = -1e30f;
                    if (c + 1 > row0 + 8) sacc[j][3] = -1e30f;
                }
            }

            // ---- online softmax ----
            float mx0 = -1e30f, mx1 = -1e30f;
            #pragma unroll
            for (int j = 0; j < 8; j++) {
                mx0 = fmaxf(mx0, fmaxf(sacc[j][0], sacc[j][1]));
                mx1 = fmaxf(mx1, fmaxf(sacc[j][2], sacc[j][3]));
            }
            mx0 = fmaxf(mx0, __shfl_xor_sync(0xffffffffu, mx0, 1));
            mx0 = fmaxf(mx0, __shfl_xor_sync(0xffffffffu, mx0, 2));
            mx1 = fmaxf(mx1, __shfl_xor_sync(0xffffffffu, mx1, 1));
            mx1 = fmaxf(mx1, __shfl_xor_sync(0xffffffffu, mx1, 2));
            const float m0n = fmaxf(m0, mx0), m1n = fmaxf(m1, mx1);
            const float a0 = __expf(m0 - m0n), a1 = __expf(m1 - m1n);
            m0 = m0n; m1 = m1n;
            float s0 = 0.f, s1 = 0.f;
            #pragma unroll
            for (int j = 0; j < 8; j++) {
                sacc[j][0] = __expf(sacc[j][0] - m0n);
                sacc[j][1] = __expf(sacc[j][1] - m0n);
                sacc[j][2] = __expf(sacc[j][2] - m1n);
                sacc[j][3] = __expf(sacc[j][3] - m1n);
                s0 += sacc[j][0] + sacc[j][1];
                s1 += sacc[j][2] + sacc[j][3];
            }
            s0 += __shfl_xor_sync(0xffffffffu, s0, 1);
            s0 += __shfl_xor_sync(0xffffffffu, s0, 2);
            s1 += __shfl_xor_sync(0xffffffffu, s1, 1);
            s1 += __shfl_xor_sync(0xffffffffu, s1, 2);
            l0 = l0 * a0 + s0;
            l1 = l1 * a1 + s1;
            #pragma unroll
            for (int j = 0; j < 8; j++) {
                oacc[j][0] *= a0; oacc[j][1] *= a0;
                oacc[j][2] *= a1; oacc[j][3] *= a1;
            }

            // ---- O += P @ V (single fp16 P and V) ----
            #pragma unroll
            for (int t = 0; t < 4; t++) {
                uint32_t pa[4];
                pa[0] = packh2(sacc[2 * t][0],     sacc[2 * t][1]);
                pa[1] = packh2(sacc[2 * t][2],     sacc[2 * t][3]);
                pa[2] = packh2(sacc[2 * t + 1][0], sacc[2 * t + 1][1]);
                pa[3] = packh2(sacc[2 * t + 1][2], sacc[2 * t + 1][3]);
                const int jq = lane >> 3;
                const int vrow = t * 16 + (jq & 1) * 8 + (lane & 7);
                #pragma unroll
                for (int g = 0; g < 4; g++) {
                    const uint32_t voff = sw128((uint32_t)(vrow * 128 + (g * 16 + (jq >> 1) * 8) * 2));
                    uint32_t v4[4];
                    ldsm4t(v4, st + FS_V + voff);
                    mma16816h(oacc[2 * g],     pa, v4[0], v4[1]);
                    mma16816h(oacc[2 * g + 1], pa, v4[2], v4[3]);
                }
            }
        }
    }

    // epilogue: normalize + single-fp16 output
    const float i0 = 1.f / l0, i1 = 1.f / l1;
    const size_t r0o = gbase + (size_t)(q0 + wid * 16 + (lane >> 2)) * DD;
    const size_t r1o = r0o + (size_t)8 * DD;
    #pragma unroll
    for (int j = 0; j < 8; j++) {
        const int c = j * 8 + (lane & 3) * 2;
        *(uint32_t*)(O + r0o + c) = packh2(oacc[j][0] * i0, oacc[j][1] * i0);
        *(uint32_t*)(O + r1o + c) = packh2(oacc[j][2] * i1, oacc[j][3] * i1);
    }
}

// ---------------- launch ----------------------------------------------------
extern "C" void kernel_launch(void* const* d_in, const int* in_sizes, int n_in,
                              void* d_out, int out_size) {
    const float* x  = (const float*)d_in[0];
    const float* Wq = (const float*)d_in[1];
    const float* bq = (const float*)d_in[2];
    const float* Wk = (const float*)d_in[3];
    const float* bk = (const float*)d_in[4];
    const float* Wv = (const float*)d_in[5];
    const float* bv = (const float*)d_in[6];
    const float* Wo = (const float*)d_in[7];
    const float* bo = (const float*)d_in[8];
    float* out = (float*)d_out;

    __half *xa, *q, *k, *v;
    __half *wqh, *wql, *wkh, *wkl, *wvh, *wvl, *woh, *wol;
    cudaGetSymbolAddress((void**)&xa, g_xa);
    cudaGetSymbolAddress((void**)&q, g_q);
    cudaGetSymbolAddress((void**)&k, g_k);
    cudaGetSymbolAddress((void**)&v, g_v);
    cudaGetSymbolAddress((void**)&wqh, g_wqh);
    cudaGetSymbolAddress((void**)&wql, g_wql);
    cudaGetSymbolAddress((void**)&wkh, g_wkh);
    cudaGetSymbolAddress((void**)&wkl, g_wkl);
    cudaGetSymbolAddress((void**)&wvh, g_wvh);
    cudaGetSymbolAddress((void**)&wvl, g_wvl);
    cudaGetSymbolAddress((void**)&woh, g_woh);
    cudaGetSymbolAddress((void**)&wol, g_wol);

    const int smem_gemm = 3 * STAGE_BYTES;   // 147456
    cudaFuncSetAttribute(gemm_qkv, cudaFuncAttributeMaxDynamicSharedMemorySize,
                         smem_gemm);
    cudaFuncSetAttribute(gemm_out, cudaFuncAttributeMaxDynamicSharedMemorySize,
                         smem_gemm);
    cudaFuncSetAttribute(flash_mma, cudaFuncAttributeMaxDynamicSharedMemorySize,
                         FA_SMEM);

    // weight split+transpose (fp16 hi/lo), all four in one launch
    wsplit_t4<<<dim3(32, 32, 4), dim3(32, 8)>>>(Wq, Wk, Wv, Wo,
                                                wqh, wql, wkh, wkl,
                                                wvh, wvl, woh, wol);

    // x -> single fp16
    tohalf<<<(MTOT * DD) / 1024, 256>>>((const float4*)x, (uint2*)xa);

    // fused QKV projections -> single fp16 (Q pre-scaled by 0.125)
    gemm_qkv<<<dim3(DD / 128, MTOT / 128, 3), 256, smem_gemm>>>(
        xa, wqh, wql, wkh, wkl, wvh, wvl, bq, bk, bv, q, k, v);

    // flash attention (single fp16) -> fp16 into xa (x no longer needed)
    flash_mma<<<dim3(NN / 128, BB * HH), 256, FA_SMEM>>>(q, k, v, xa);

    // output projection -> fp32 out
    gemm_out<<<dim3(DD / 128, MTOT / 128), 256, smem_gemm>>>(xa, woh, wol, bo, out);
}